// round 9
// baseline (speedup 1.0000x reference)
#include <cuda_runtime.h>
#include <cuda_bf16.h>
#include <cstdint>

#define kS 3072
#define kD 512
#define kH 8

__device__ __nv_bfloat16 g_qc[(size_t)kH * kS * 192];
__device__ __nv_bfloat16 g_kc[(size_t)kH * kS * 192];
__device__ float g_v[(size_t)kH * kS * 64];
__device__ float g_ctx[(size_t)kS * kD];
// prepass outputs
__device__ __nv_bfloat16 g_xh[(size_t)kS * kD];
__device__ __nv_bfloat16 g_xl[(size_t)kS * kD];
__device__ __nv_bfloat16 g_wth[(size_t)3 * kD * kD];   // [z][n][k]
__device__ __nv_bfloat16 g_wtl[(size_t)3 * kD * kD];

// ======================= warp-MMA helpers (sm_80+ path) =======================
__device__ __forceinline__ uint32_t smem_u32(const void* p) {
    uint32_t a;
    asm("{ .reg .u64 t; cvta.to.shared.u64 t, %1; cvt.u32.u64 %0, t; }" : "=r"(a) : "l"(p));
    return a;
}
__device__ __forceinline__ void ldm_x4(uint32_t* r, uint32_t addr) {
    asm volatile("ldmatrix.sync.aligned.m8n8.x4.shared.b16 {%0,%1,%2,%3}, [%4];"
                 : "=r"(r[0]), "=r"(r[1]), "=r"(r[2]), "=r"(r[3]) : "r"(addr));
}
__device__ __forceinline__ void mma16816(float* c, const uint32_t* a, uint32_t b0, uint32_t b1) {
    asm volatile("mma.sync.aligned.m16n8k16.row.col.f32.bf16.bf16.f32 "
                 "{%0,%1,%2,%3}, {%4,%5,%6,%7}, {%8,%9}, {%0,%1,%2,%3};"
                 : "+f"(c[0]), "+f"(c[1]), "+f"(c[2]), "+f"(c[3])
                 : "r"(a[0]), "r"(a[1]), "r"(a[2]), "r"(a[3]), "r"(b0), "r"(b1));
}
__device__ __forceinline__ void split4(float4 f, uint32_t& h01, uint32_t& h23,
                                       uint32_t& l01, uint32_t& l23) {
    __nv_bfloat16 h0 = __float2bfloat16(f.x);
    __nv_bfloat16 h1 = __float2bfloat16(f.y);
    __nv_bfloat16 h2 = __float2bfloat16(f.z);
    __nv_bfloat16 h3 = __float2bfloat16(f.w);
    __nv_bfloat16 l0 = __float2bfloat16(f.x - __bfloat162float(h0));
    __nv_bfloat16 l1 = __float2bfloat16(f.y - __bfloat162float(h1));
    __nv_bfloat16 l2 = __float2bfloat16(f.z - __bfloat162float(h2));
    __nv_bfloat16 l3 = __float2bfloat16(f.w - __bfloat162float(h3));
    h01 = ((uint32_t)__bfloat16_as_ushort(h1) << 16) | __bfloat16_as_ushort(h0);
    h23 = ((uint32_t)__bfloat16_as_ushort(h3) << 16) | __bfloat16_as_ushort(h2);
    l01 = ((uint32_t)__bfloat16_as_ushort(l1) << 16) | __bfloat16_as_ushort(l0);
    l23 = ((uint32_t)__bfloat16_as_ushort(l3) << 16) | __bfloat16_as_ushort(l2);
}
__device__ __forceinline__ void split2(float a, float b, uint32_t& hh, uint32_t& ll) {
    __nv_bfloat16 h0 = __float2bfloat16(a);
    __nv_bfloat16 h1 = __float2bfloat16(b);
    __nv_bfloat16 l0 = __float2bfloat16(a - __bfloat162float(h0));
    __nv_bfloat16 l1 = __float2bfloat16(b - __bfloat162float(h1));
    hh = ((uint32_t)__bfloat16_as_ushort(h1) << 16) | __bfloat16_as_ushort(h0);
    ll = ((uint32_t)__bfloat16_as_ushort(l1) << 16) | __bfloat16_as_ushort(l0);
}

// ================= Prepass A: x -> hi/lo bf16 =================
__global__ __launch_bounds__(256) void xsplit_kernel(const float* __restrict__ x)
{
    int i = blockIdx.x * 256 + threadIdx.x;   // over float4s
    float4 v = ((const float4*)x)[i];
    uint32_t h01, h23, l01, l23;
    split4(v, h01, h23, l01, l23);
    ((uint2*)g_xh)[i] = make_uint2(h01, h23);
    ((uint2*)g_xl)[i] = make_uint2(l01, l23);
}

// ================= Prepass B: W -> transposed hi/lo bf16 [z][n][k] =================
__global__ __launch_bounds__(256) void wsplit_kernel(
    const float* __restrict__ Wq, const float* __restrict__ Wk, const float* __restrict__ Wv)
{
    const int z = blockIdx.y;
    const float* W = (z == 0) ? Wq : (z == 1) ? Wk : Wv;
    int i = blockIdx.x * 256 + threadIdx.x;   // 512*128 per z
    int n = i >> 7;
    int kq = (i & 127) * 4;
    float4 v;
    v.x = W[(size_t)(kq + 0) * kD + n];
    v.y = W[(size_t)(kq + 1) * kD + n];
    v.z = W[(size_t)(kq + 2) * kD + n];
    v.w = W[(size_t)(kq + 3) * kD + n];
    uint32_t h01, h23, l01, l23;
    split4(v, h01, h23, l01, l23);
    size_t o = ((size_t)z * kD + n) * kD + kq;
    *(uint2*)&g_wth[o] = make_uint2(h01, h23);
    *(uint2*)&g_wtl[o] = make_uint2(l01, l23);
}

// ================= Kernel 1: QKV projections (HMMA, split-bf16) =================
// CTA 64 rows x 64 cols (one head); 8 warps 4m x 2n (m16n32); K=512, 8 chunks of 64.
#define QK_STR 72
__global__ __launch_bounds__(256) void qkv_kernel(
    const float* __restrict__ bq, const float* __restrict__ bk, const float* __restrict__ bv)
{
    __shared__ __align__(16) char s[4 * 64 * QK_STR * 2];
    char* sAh = s;
    char* sAl = s + 64 * QK_STR * 2;
    char* sBh = s + 2 * 64 * QK_STR * 2;
    char* sBl = s + 3 * 64 * QK_STR * 2;

    const int m0 = blockIdx.x * 64;
    const int h  = blockIdx.y;
    const int z  = blockIdx.z;
    const int n0 = h * 64;
    const float* bias = (z == 0) ? bq : (z == 1) ? bk : bv;
    const float scale = (z == 0) ? 0.125f : 1.0f;

    const int tid = threadIdx.x, wid = tid >> 5, lane = tid & 31;
    const uint32_t ahB = smem_u32(sAh), alB = smem_u32(sAl);
    const uint32_t bhB = smem_u32(sBh), blB = smem_u32(sBl);

    const int wm = (wid & 3) * 16;
    const int wn = (wid >> 2) * 32;
    const int arow = lane & 15, ak = (lane >> 4) * 8;

    float acc[4][4];
    #pragma unroll
    for (int j = 0; j < 4; j++)
        #pragma unroll
        for (int q = 0; q < 4; q++) acc[j][q] = 0.f;

    #pragma unroll 1
    for (int k0 = 0; k0 < kD; k0 += 64) {
        __syncthreads();
        #pragma unroll
        for (int t = 0; t < 4; t++) {
            int i = tid + t * 256;          // 0..1023
            int r = i >> 4, c4 = (i & 15) * 4;
            uint32_t off = (uint32_t)r * (QK_STR * 2) + (uint32_t)c4 * 2;
            size_t ax = (size_t)(m0 + r) * kD + k0 + c4;
            *(uint2*)(sAh + off) = *(const uint2*)&g_xh[ax];
            *(uint2*)(sAl + off) = *(const uint2*)&g_xl[ax];
            size_t bx = ((size_t)z * kD + n0 + r) * kD + k0 + c4;
            *(uint2*)(sBh + off) = *(const uint2*)&g_wth[bx];
            *(uint2*)(sBl + off) = *(const uint2*)&g_wtl[bx];
        }
        __syncthreads();

        #pragma unroll
        for (int ks = 0; ks < 4; ks++) {
            uint32_t koff = (uint32_t)(ks * 16 + ak) * 2;
            uint32_t ah[4], al[4];
            ldm_x4(ah, ahB + (uint32_t)(wm + arow) * (QK_STR * 2) + koff);
            ldm_x4(al, alB + (uint32_t)(wm + arow) * (QK_STR * 2) + koff);
            uint32_t bh[2][4], bl[2][4];
            #pragma unroll
            for (int nb = 0; nb < 2; nb++) {
                ldm_x4(bh[nb], bhB + (uint32_t)(wn + nb * 16 + arow) * (QK_STR * 2) + koff);
                ldm_x4(bl[nb], blB + (uint32_t)(wn + nb * 16 + arow) * (QK_STR * 2) + koff);
            }
            #pragma unroll
            for (int nb = 0; nb < 2; nb++) {
                mma16816(acc[nb * 2 + 0], ah, bh[nb][0], bh[nb][2]);
                mma16816(acc[nb * 2 + 1], ah, bh[nb][1], bh[nb][3]);
                mma16816(acc[nb * 2 + 0], ah, bl[nb][0], bl[nb][2]);
                mma16816(acc[nb * 2 + 1], ah, bl[nb][1], bl[nb][3]);
                mma16816(acc[nb * 2 + 0], al, bh[nb][0], bh[nb][2]);
                mma16816(acc[nb * 2 + 1], al, bh[nb][1], bh[nb][3]);
            }
        }
    }

    const int gId = lane >> 2, tig = lane & 3;
    if (z == 2) {
        #pragma unroll
        for (int nf = 0; nf < 4; nf++) {
            int dkc = wn + nf * 8 + tig * 2;
            int m_lo = m0 + wm + gId;
            float b0v = bias[n0 + dkc], b1v = bias[n0 + dkc + 1];
            *(float2*)&g_v[((size_t)h * kS + m_lo) * 64 + dkc] =
                make_float2(acc[nf][0] + b0v, acc[nf][1] + b1v);
            *(float2*)&g_v[((size_t)h * kS + m_lo + 8) * 64 + dkc] =
                make_float2(acc[nf][2] + b0v, acc[nf][3] + b1v);
        }
    } else {
        __nv_bfloat16* dstc = (z == 0) ? g_qc : g_kc;
        const bool isq = (z == 0);
        #pragma unroll
        for (int nf = 0; nf < 4; nf++) {
            int dkc = wn + nf * 8 + tig * 2;
            float b0v = bias[n0 + dkc], b1v = bias[n0 + dkc + 1];
            #pragma unroll
            for (int half = 0; half < 2; half++) {
                int m = m0 + wm + gId + half * 8;
                float v0 = (acc[nf][half * 2 + 0] + b0v) * scale;
                float v1 = (acc[nf][half * 2 + 1] + b1v) * scale;
                uint32_t hh, ll;
                split2(v0, v1, hh, ll);
                size_t base = ((size_t)h * kS + m) * 192 + dkc;
                *(uint32_t*)&dstc[base] = hh;
                if (isq) { *(uint32_t*)&dstc[base + 64] = hh; *(uint32_t*)&dstc[base + 128] = ll; }
                else     { *(uint32_t*)&dstc[base + 64] = ll; *(uint32_t*)&dstc[base + 128] = hh; }
            }
        }
    }
}

// ================= Kernel 2: logits = Qcat @ Kcat^T (HMMA, m64n64 warps) =================
// CTA 128x128, 4 warps (2m x 2n), each warp m64 x n64, K=192.
#define LG_ASTR 200
#define LG_SA   0
#define LG_SB   (128 * LG_ASTR * 2)
#define LG_SMEM (2 * 128 * LG_ASTR * 2)

__global__ __launch_bounds__(128, 2) void logits_kernel(float* __restrict__ logits)
{
    extern __shared__ char sm[];
    char* smA = sm + LG_SA;
    char* smB = sm + LG_SB;

    const int tid = threadIdx.x, wid = tid >> 5, lane = tid & 31;
    const int h = blockIdx.z;
    const int row0 = blockIdx.y * 128;
    const int col0 = blockIdx.x * 128;

    // load A/B tiles (K=192 = 24 uint4 per row), 128 threads
    #pragma unroll
    for (int t = 0; t < 24; t++) {
        int i = tid + t * 128;           // 0..3071
        int r = i / 24, cp = i % 24;
        *(uint4*)(smA + r * (LG_ASTR * 2) + cp * 16) =
            *(const uint4*)&g_qc[((size_t)h * kS + row0 + r) * 192 + cp * 8];
        *(uint4*)(smB + r * (LG_ASTR * 2) + cp * 16) =
            *(const uint4*)&g_kc[((size_t)h * kS + col0 + r) * 192 + cp * 8];
    }
    __syncthreads();

    const int wm = (wid & 1) * 64;
    const int wn = (wid >> 1) * 64;
    const uint32_t saBase = smem_u32(smA);
    const uint32_t sbBase = smem_u32(smB);

    float acc[4][8][4];
    #pragma unroll
    for (int i = 0; i < 4; i++)
        #pragma unroll
        for (int j = 0; j < 8; j++)
            #pragma unroll
            for (int q = 0; q < 4; q++) acc[i][j][q] = 0.f;

    const int arow = lane & 15, ak = (lane >> 4) * 8;
    #pragma unroll 1
    for (int ks = 0; ks < 12; ks++) {
        uint32_t koff = (uint32_t)(ks * 16 + ak) * 2;
        uint32_t a[4][4];
        #pragma unroll
        for (int mi = 0; mi < 4; mi++)
            ldm_x4(a[mi], saBase + (uint32_t)(wm + mi * 16 + arow) * 400 + koff);
        uint32_t b[4][4];
        #pragma unroll
        for (int nb = 0; nb < 4; nb++)
            ldm_x4(b[nb], sbBase + (uint32_t)(wn + nb * 16 + arow) * 400 + koff);
        #pragma unroll
        for (int mi = 0; mi < 4; mi++) {
            #pragma unroll
            for (int nb = 0; nb < 4; nb++) {
                mma16816(acc[mi][nb * 2 + 0], a[mi], b[nb][0], b[nb][2]);
                mma16816(acc[mi][nb * 2 + 1], a[mi], b[nb][1], b[nb][3]);
            }
        }
    }

    const int gId = lane >> 2, tig = lane & 3;
    #pragma unroll
    for (int mi = 0; mi < 4; mi++) {
        #pragma unroll
        for (int nf = 0; nf < 8; nf++) {
            int c = col0 + wn + nf * 8 + tig * 2;
            int r_lo = row0 + wm + mi * 16 + gId;
            *(float2*)&logits[((size_t)h * kS + r_lo) * kS + c] =
                make_float2(acc[mi][nf][0], acc[mi][nf][1]);
            *(float2*)&logits[((size_t)h * kS + r_lo + 8) * kS + c] =
                make_float2(acc[mi][nf][2], acc[mi][nf][3]);
        }
    }
}

// ================= Kernel 3: entmax1.5, register-resident rows =================
__global__ __launch_bounds__(256, 1) void entmax_kernel(float* __restrict__ attn)
{
    const int h = blockIdx.y;
    const int tid = threadIdx.x, wid = tid >> 5, lane = tid & 31;
    const int row = blockIdx.x * 8 + wid;
    float4* rp = (float4*)(attn + ((size_t)(h * kS + row)) * kS);

    float4 v[24];
    #pragma unroll
    for (int i = 0; i < 24; i++) v[i] = rp[lane + i * 32];

    float mx = -3.4e38f;
    #pragma unroll
    for (int i = 0; i < 24; i++)
        mx = fmaxf(mx, fmaxf(fmaxf(v[i].x, v[i].y), fmaxf(v[i].z, v[i].w)));
    #pragma unroll
    for (int o = 16; o; o >>= 1) mx = fmaxf(mx, __shfl_xor_sync(0xffffffffu, mx, o));

    float sum = 0.f;
    #pragma unroll
    for (int i = 0; i < 24; i++) {
        v[i].x = (v[i].x - mx) * 0.5f; v[i].y = (v[i].y - mx) * 0.5f;
        v[i].z = (v[i].z - mx) * 0.5f; v[i].w = (v[i].w - mx) * 0.5f;
        sum += (v[i].x + v[i].y) + (v[i].z + v[i].w);
    }
    #pragma unroll
    for (int o = 16; o; o >>= 1) sum += __shfl_xor_sync(0xffffffffu, sum, o);

    float tau = fminf(fmaxf(sum * (1.0f / kS), -1.0f), -1e-6f);
    #pragma unroll 1
    for (int it = 0; it < 12; it++) {
        float g = 0.f, gp = 0.f;
        #pragma unroll
        for (int i = 0; i < 24; i++) {
            float t0 = fmaxf(v[i].x - tau, 0.f); g = fmaf(t0, t0, g); gp += t0;
            float t1 = fmaxf(v[i].y - tau, 0.f); g = fmaf(t1, t1, g); gp += t1;
            float t2 = fmaxf(v[i].z - tau, 0.f); g = fmaf(t2, t2, g); gp += t2;
            float t3 = fmaxf(v[i].w - tau, 0.f); g = fmaf(t3, t3, g); gp += t3;
        }
        #pragma unroll
        for (int o = 16; o; o >>= 1) {
            g  += __shfl_xor_sync(0xffffffffu, g, o);
            gp += __shfl_xor_sync(0xffffffffu, gp, o);
        }
        tau = tau + (g - 1.0f) / fmaxf(2.f * gp, 1e-20f);
        tau = fminf(fmaxf(tau, -1.0f), 0.0f);
    }

    #pragma unroll
    for (int i = 0; i < 24; i++) {
        float t;
        t = fmaxf(v[i].x - tau, 0.f); v[i].x = t * t;
        t = fmaxf(v[i].y - tau, 0.f); v[i].y = t * t;
        t = fmaxf(v[i].z - tau, 0.f); v[i].z = t * t;
        t = fmaxf(v[i].w - tau, 0.f); v[i].w = t * t;
        rp[lane + i * 32] = v[i];
    }
}

// ================= Kernel 4: ctx = P @ V (HMMA, double-buffered) =================
// CTA: 64 rows x 64 cols; 8 warps: wm=(wid&3)*16, wn=(wid>>2)*32. K chunks of 64.
#define PV_STR   72
#define PV_STAGE (4 * 64 * PV_STR * 2)     // Ah|Al|Bh|Bl per stage = 36864 B
#define PV_SMEM  (2 * PV_STAGE)

__global__ __launch_bounds__(256, 2) void pv_kernel(const float* __restrict__ p)
{
    extern __shared__ char sm[];

    const int tid = threadIdx.x, wid = tid >> 5, lane = tid & 31;
    const int h = blockIdx.y;
    const int row0 = blockIdx.x * 64;

    float acc[4][4];
    #pragma unroll
    for (int j = 0; j < 4; j++)
        #pragma unroll
        for (int q = 0; q < 4; q++) acc[j][q] = 0.f;

    const int arow = lane & 15, ak = (lane >> 4) * 8;
    const int wm = (wid & 3) * 16;
    const int wn = (wid >> 2) * 32;

    const int pr0 = tid >> 4;
    const int pc4 = (tid & 15) * 4;
    const int vj  = tid & 63;
    const int vd0 = (tid >> 6) * 4;

    float4 pf_p[4], pf_v[4];

    // ---- prologue: load + convert chunk 0 into stage 0 ----
    {
        char* smAh = sm;
        char* smAl = sm + 64 * PV_STR * 2;
        char* smBh = sm + 2 * 64 * PV_STR * 2;
        char* smBl = sm + 3 * 64 * PV_STR * 2;
        #pragma unroll
        for (int t = 0; t < 4; t++) {
            pf_p[t] = *(const float4*)&p[((size_t)h * kS + row0 + pr0 + t * 16) * kS + pc4];
            pf_v[t] = *(const float4*)&g_v[((size_t)h * kS + vj) * 64 + vd0 + t * 16];
        }
        #pragma unroll
        for (int t = 0; t < 4; t++) {
            uint32_t h01, h23, l01, l23;
            split4(pf_p[t], h01, h23, l01, l23);
            uint32_t off = (uint32_t)(pr0 + t * 16) * (PV_STR * 2) + (uint32_t)pc4 * 2;
            *(uint2*)(smAh + off) = make_uint2(h01, h23);
            *(uint2*)(smAl + off) = make_uint2(l01, l23);
            float f[4] = {pf_v[t].x, pf_v[t].y, pf_v[t].z, pf_v[t].w};
            #pragma unroll
            for (int q = 0; q < 4; q++) {
                __nv_bfloat16 hb = __float2bfloat16(f[q]);
                __nv_bfloat16 lb = __float2bfloat16(f[q] - __bfloat162float(hb));
                *(__nv_bfloat16*)(smBh + (vd0 + t * 16 + q) * (PV_STR * 2) + vj * 2) = hb;
                *(__nv_bfloat16*)(smBl + (vd0 + t * 16 + q) * (PV_STR * 2) + vj * 2) = lb;
            }
        }
    }
    __syncthreads();

    #pragma unroll 1
    for (int c = 0; c < 48; c++) {
        char* rd = sm + (c & 1) * PV_STAGE;
        char* wr = sm + ((c + 1) & 1) * PV_STAGE;
        const uint32_t ahB = smem_u32(rd);
        const uint32_t alB = ahB + 64 * PV_STR * 2;
        const uint32_t bhB = ahB + 2 * 64 * PV_STR * 2;
        const uint32_t blB = ahB + 3 * 64 * PV_STR * 2;

        // prefetch next chunk into registers
        if (c < 47) {
            const int j0 = (c + 1) * 64;
            #pragma unroll
            for (int t = 0; t < 4; t++) {
                pf_p[t] = *(const float4*)&p[((size_t)h * kS + row0 + pr0 + t * 16) * kS + j0 + pc4];
                pf_v[t] = *(const float4*)&g_v[((size_t)h * kS + j0 + vj) * 64 + vd0 + t * 16];
            }
        }

        // compute chunk c from read stage
        #pragma unroll
        for (int ks = 0; ks < 4; ks++) {
            uint32_t koff = (uint32_t)(ks * 16 + ak) * 2;
            uint32_t ah[4], al[4];
            ldm_x4(ah, ahB + (uint32_t)(wm + arow) * (PV_STR * 2) + koff);
            ldm_x4(al, alB + (uint32_t)(wm + arow) * (PV_STR * 2) + koff);
            uint32_t bh[2][4], bl[2][4];
            #pragma unroll
            for (int nb = 0; nb < 2; nb++) {
                ldm_x4(bh[nb], bhB + (uint32_t)(wn + nb * 16 + arow) * (PV_STR * 2) + koff);
                ldm_x4(bl[nb], blB + (uint32_t)(wn + nb * 16 + arow) * (PV_STR * 2) + koff);
            }
            #pragma unroll
            for (int nb = 0; nb < 2; nb++) {
                mma16816(acc[nb * 2 + 0], ah, bh[nb][0], bh[nb][2]);
                mma16816(acc[nb * 2 + 1], ah, bh[nb][1], bh[nb][3]);
                mma16816(acc[nb * 2 + 0], ah, bl[nb][0], bl[nb][2]);
                mma16816(acc[nb * 2 + 1], ah, bl[nb][1], bl[nb][3]);
                mma16816(acc[nb * 2 + 0], al, bh[nb][0], bh[nb][2]);
                mma16816(acc[nb * 2 + 1], al, bh[nb][1], bh[nb][3]);
            }
        }

        // convert + store prefetched chunk into write stage
        if (c < 47) {
            char* smAh = wr;
            char* smAl = wr + 64 * PV_STR * 2;
            char* smBh = wr + 2 * 64 * PV_STR * 2;
            char* smBl = wr + 3 * 64 * PV_STR * 2;
            #pragma unroll
            for (int t = 0; t < 4; t++) {
                uint32_t h01, h23, l01, l23;
                split4(pf_p[t], h01, h23, l01, l23);
                uint32_t off = (uint32_t)(pr0 + t * 16) * (PV_STR * 2) + (uint32_t)pc4 * 2;
                *(uint2*)(smAh + off) = make_uint2(h01, h23);
                *(uint2*)(smAl + off) = make_uint2(l01, l23);
                float f[4] = {pf_v[t].x, pf_v[t].y, pf_v[t].z, pf_v[t].w};
                #pragma unroll
                for (int q = 0; q < 4; q++) {
                    __nv_bfloat16 hb = __float2bfloat16(f[q]);
                    __nv_bfloat16 lb = __float2bfloat16(f[q] - __bfloat162float(hb));
                    *(__nv_bfloat16*)(smBh + (vd0 + t * 16 + q) * (PV_STR * 2) + vj * 2) = hb;
                    *(__nv_bfloat16*)(smBl + (vd0 + t * 16 + q) * (PV_STR * 2) + vj * 2) = lb;
                }
            }
        }
        __syncthreads();
    }

    const int gId = lane >> 2, tig = lane & 3;
    #pragma unroll
    for (int f = 0; f < 4; f++) {
        int cc = wn + (f >> 1) * 16 + (f & 1) * 8 + tig * 2;
        int r_lo = row0 + wm + gId;
        *(float2*)&g_ctx[(size_t)r_lo * kD + h * 64 + cc] =
            make_float2(acc[f][0], acc[f][1]);
        *(float2*)&g_ctx[(size_t)(r_lo + 8) * kD + h * 64 + cc] =
            make_float2(acc[f][2], acc[f][3]);
    }
}

// ================= Kernel 5: Wo GEMM + residual + LN =================
__global__ __launch_bounds__(256) void out_kernel(
    const float* __restrict__ x,
    const float* __restrict__ Wo, const float* __restrict__ bo,
    const float* __restrict__ gamma, const float* __restrict__ beta,
    float* __restrict__ out)
{
    __shared__ float sC[16 * kD];

    const int m0  = blockIdx.x * 16;
    const int tid = threadIdx.x;

    for (int i = tid; i < 2048; i += 256)
        ((float4*)sC)[i] = ((const float4*)&g_ctx[(size_t)m0 * kD])[i];
    __syncthreads();

    const int n0 = tid, n1 = tid + 256;
    float acc0[16], acc1[16];
    #pragma unroll
    for (int r = 0; r < 16; r++) { acc0[r] = 0.f; acc1[r] = 0.f; }

    for (int k = 0; k < kD; k += 4) {
        float w0[4], w1[4];
        #pragma unroll
        for (int kk = 0; kk < 4; kk++) {
            w0[kk] = Wo[(size_t)(k + kk) * kD + n0];
            w1[kk] = Wo[(size_t)(k + kk) * kD + n1];
        }
        #pragma unroll
        for (int r = 0; r < 16; r++) {
            float4 cv4 = *(const float4*)&sC[r * kD + k];
            float cv[4] = {cv4.x, cv4.y, cv4.z, cv4.w};
            #pragma unroll
            for (int kk = 0; kk < 4; kk++) {
                acc0[r] = fmaf(cv[kk], w0[kk], acc0[r]);
                acc1[r] = fmaf(cv[kk], w1[kk], acc1[r]);
            }
        }
    }
    __syncthreads();

    const float b0v = bo[n0], b1v = bo[n1];
    #pragma unroll
    for (int r = 0; r < 16; r++) {
        sC[r * kD + n0] = acc0[r] + b0v + x[(size_t)(m0 + r) * kD + n0];
        sC[r * kD + n1] = acc1[r] + b1v + x[(size_t)(m0 + r) * kD + n1];
    }
    __syncthreads();

    const int wid = tid >> 5, lane = tid & 31;
    #pragma unroll 1
    for (int rr = 0; rr < 2; rr++) {
        int r = wid * 2 + rr;
        float s = 0.f, ss = 0.f;
        for (int i = lane; i < kD; i += 32) {
            float v = sC[r * kD + i];
            s += v; ss = fmaf(v, v, ss);
        }
        #pragma unroll
        for (int o = 16; o; o >>= 1) {
            s  += __shfl_xor_sync(0xffffffffu, s, o);
            ss += __shfl_xor_sync(0xffffffffu, ss, o);
        }
        float mu  = s * (1.f / kD);
        float var = ss * (1.f / kD) - mu * mu;
        float inv = rsqrtf(var + 1e-6f);
        for (int i = lane; i < kD; i += 32) {
            float v = sC[r * kD + i];
            out[(size_t)(m0 + r) * kD + i] = (v - mu) * inv * gamma[i] + beta[i];
        }
    }
}

// ================= launcher =================
extern "C" void kernel_launch(void* const* d_in, const int* in_sizes, int n_in,
                              void* d_out, int out_size)
{
    const float* x     = (const float*)d_in[0];
    const float* Wq    = (const float*)d_in[1];
    const float* bq    = (const float*)d_in[2];
    const float* Wk    = (const float*)d_in[3];
    const float* bk    = (const float*)d_in[4];
    const float* Wv    = (const float*)d_in[5];
    const float* bv    = (const float*)d_in[6];
    const float* Wo    = (const float*)d_in[7];
    const float* bo    = (const float*)d_in[8];
    const float* gamma = (const float*)d_in[9];
    const float* beta  = (const float*)d_in[10];

    float* out  = (float*)d_out;
    float* attn = out + (size_t)kS * kD;

    cudaFuncSetAttribute(logits_kernel, cudaFuncAttributeMaxDynamicSharedMemorySize, LG_SMEM);
    cudaFuncSetAttribute(pv_kernel,     cudaFuncAttributeMaxDynamicSharedMemorySize, PV_SMEM);

    xsplit_kernel<<<kS * kD / 4 / 256, 256>>>(x);
    wsplit_kernel<<<dim3(kD * kD / 4 / 256, 3), 256>>>(Wq, Wk, Wv);
    qkv_kernel<<<dim3(48, 8, 3), 256>>>(bq, bk, bv);
    logits_kernel<<<dim3(24, 24, 8), 128, LG_SMEM>>>(attn);
    entmax_kernel<<<dim3(kS / 8, kH), 256>>>(attn);
    pv_kernel<<<dim3(48, 8), 256, PV_SMEM>>>(attn);
    out_kernel<<<kS / 16, 256>>>(x, Wo, bo, gamma, beta, out);
}

// round 10
// speedup vs baseline: 1.0793x; 1.0793x over previous
#include <cuda_runtime.h>
#include <cuda_bf16.h>
#include <cstdint>

#define kS 3072
#define kD 512
#define kH 8
#define NEWT 8

__device__ __nv_bfloat16 g_qc[(size_t)kH * kS * 192];
__device__ __nv_bfloat16 g_kc[(size_t)kH * kS * 192];
__device__ float g_v[(size_t)kH * kS * 64];
__device__ float g_ctx[(size_t)kS * kD];
// prepass outputs
__device__ __nv_bfloat16 g_xh[(size_t)kS * kD];
__device__ __nv_bfloat16 g_xl[(size_t)kS * kD];
__device__ __nv_bfloat16 g_wth[(size_t)3 * kD * kD];   // [z][n][k]
__device__ __nv_bfloat16 g_wtl[(size_t)3 * kD * kD];

// ======================= warp-MMA helpers (sm_80+ path) =======================
__device__ __forceinline__ uint32_t smem_u32(const void* p) {
    uint32_t a;
    asm("{ .reg .u64 t; cvta.to.shared.u64 t, %1; cvt.u32.u64 %0, t; }" : "=r"(a) : "l"(p));
    return a;
}
__device__ __forceinline__ void ldm_x4(uint32_t* r, uint32_t addr) {
    asm volatile("ldmatrix.sync.aligned.m8n8.x4.shared.b16 {%0,%1,%2,%3}, [%4];"
                 : "=r"(r[0]), "=r"(r[1]), "=r"(r[2]), "=r"(r[3]) : "r"(addr));
}
__device__ __forceinline__ void mma16816(float* c, const uint32_t* a, uint32_t b0, uint32_t b1) {
    asm volatile("mma.sync.aligned.m16n8k16.row.col.f32.bf16.bf16.f32 "
                 "{%0,%1,%2,%3}, {%4,%5,%6,%7}, {%8,%9}, {%0,%1,%2,%3};"
                 : "+f"(c[0]), "+f"(c[1]), "+f"(c[2]), "+f"(c[3])
                 : "r"(a[0]), "r"(a[1]), "r"(a[2]), "r"(a[3]), "r"(b0), "r"(b1));
}
__device__ __forceinline__ void split4(float4 f, uint32_t& h01, uint32_t& h23,
                                       uint32_t& l01, uint32_t& l23) {
    __nv_bfloat16 h0 = __float2bfloat16(f.x);
    __nv_bfloat16 h1 = __float2bfloat16(f.y);
    __nv_bfloat16 h2 = __float2bfloat16(f.z);
    __nv_bfloat16 h3 = __float2bfloat16(f.w);
    __nv_bfloat16 l0 = __float2bfloat16(f.x - __bfloat162float(h0));
    __nv_bfloat16 l1 = __float2bfloat16(f.y - __bfloat162float(h1));
    __nv_bfloat16 l2 = __float2bfloat16(f.z - __bfloat162float(h2));
    __nv_bfloat16 l3 = __float2bfloat16(f.w - __bfloat162float(h3));
    h01 = ((uint32_t)__bfloat16_as_ushort(h1) << 16) | __bfloat16_as_ushort(h0);
    h23 = ((uint32_t)__bfloat16_as_ushort(h3) << 16) | __bfloat16_as_ushort(h2);
    l01 = ((uint32_t)__bfloat16_as_ushort(l1) << 16) | __bfloat16_as_ushort(l0);
    l23 = ((uint32_t)__bfloat16_as_ushort(l3) << 16) | __bfloat16_as_ushort(l2);
}
__device__ __forceinline__ void split2(float a, float b, uint32_t& hh, uint32_t& ll) {
    __nv_bfloat16 h0 = __float2bfloat16(a);
    __nv_bfloat16 h1 = __float2bfloat16(b);
    __nv_bfloat16 l0 = __float2bfloat16(a - __bfloat162float(h0));
    __nv_bfloat16 l1 = __float2bfloat16(b - __bfloat162float(h1));
    hh = ((uint32_t)__bfloat16_as_ushort(h1) << 16) | __bfloat16_as_ushort(h0);
    ll = ((uint32_t)__bfloat16_as_ushort(l1) << 16) | __bfloat16_as_ushort(l0);
}

// ================= Prepass A: x -> hi/lo bf16 =================
__global__ __launch_bounds__(256) void xsplit_kernel(const float* __restrict__ x)
{
    int i = blockIdx.x * 256 + threadIdx.x;   // over float4s
    float4 v = ((const float4*)x)[i];
    uint32_t h01, h23, l01, l23;
    split4(v, h01, h23, l01, l23);
    ((uint2*)g_xh)[i] = make_uint2(h01, h23);
    ((uint2*)g_xl)[i] = make_uint2(l01, l23);
}

// ================= Prepass B: W -> transposed hi/lo bf16 [z][n][k] =================
__global__ __launch_bounds__(256) void wsplit_kernel(
    const float* __restrict__ Wq, const float* __restrict__ Wk, const float* __restrict__ Wv)
{
    const int z = blockIdx.y;
    const float* W = (z == 0) ? Wq : (z == 1) ? Wk : Wv;
    int i = blockIdx.x * 256 + threadIdx.x;   // 512*128 per z
    int n = i >> 7;
    int kq = (i & 127) * 4;
    float4 v;
    v.x = W[(size_t)(kq + 0) * kD + n];
    v.y = W[(size_t)(kq + 1) * kD + n];
    v.z = W[(size_t)(kq + 2) * kD + n];
    v.w = W[(size_t)(kq + 3) * kD + n];
    uint32_t h01, h23, l01, l23;
    split4(v, h01, h23, l01, l23);
    size_t o = ((size_t)z * kD + n) * kD + kq;
    *(uint2*)&g_wth[o] = make_uint2(h01, h23);
    *(uint2*)&g_wtl[o] = make_uint2(l01, l23);
}

// ================= Kernel 1: QKV projections (HMMA, split-bf16) =================
#define QK_STR 72
__global__ __launch_bounds__(256) void qkv_kernel(
    const float* __restrict__ bq, const float* __restrict__ bk, const float* __restrict__ bv)
{
    __shared__ __align__(16) char s[4 * 64 * QK_STR * 2];
    char* sAh = s;
    char* sAl = s + 64 * QK_STR * 2;
    char* sBh = s + 2 * 64 * QK_STR * 2;
    char* sBl = s + 3 * 64 * QK_STR * 2;

    const int m0 = blockIdx.x * 64;
    const int h  = blockIdx.y;
    const int z  = blockIdx.z;
    const int n0 = h * 64;
    const float* bias = (z == 0) ? bq : (z == 1) ? bk : bv;
    const float scale = (z == 0) ? 0.125f : 1.0f;

    const int tid = threadIdx.x, wid = tid >> 5, lane = tid & 31;
    const uint32_t ahB = smem_u32(sAh), alB = smem_u32(sAl);
    const uint32_t bhB = smem_u32(sBh), blB = smem_u32(sBl);

    const int wm = (wid & 3) * 16;
    const int wn = (wid >> 2) * 32;
    const int arow = lane & 15, ak = (lane >> 4) * 8;

    float acc[4][4];
    #pragma unroll
    for (int j = 0; j < 4; j++)
        #pragma unroll
        for (int q = 0; q < 4; q++) acc[j][q] = 0.f;

    #pragma unroll 1
    for (int k0 = 0; k0 < kD; k0 += 64) {
        __syncthreads();
        #pragma unroll
        for (int t = 0; t < 4; t++) {
            int i = tid + t * 256;          // 0..1023
            int r = i >> 4, c4 = (i & 15) * 4;
            uint32_t off = (uint32_t)r * (QK_STR * 2) + (uint32_t)c4 * 2;
            size_t ax = (size_t)(m0 + r) * kD + k0 + c4;
            *(uint2*)(sAh + off) = *(const uint2*)&g_xh[ax];
            *(uint2*)(sAl + off) = *(const uint2*)&g_xl[ax];
            size_t bx = ((size_t)z * kD + n0 + r) * kD + k0 + c4;
            *(uint2*)(sBh + off) = *(const uint2*)&g_wth[bx];
            *(uint2*)(sBl + off) = *(const uint2*)&g_wtl[bx];
        }
        __syncthreads();

        #pragma unroll
        for (int ks = 0; ks < 4; ks++) {
            uint32_t koff = (uint32_t)(ks * 16 + ak) * 2;
            uint32_t ah[4], al[4];
            ldm_x4(ah, ahB + (uint32_t)(wm + arow) * (QK_STR * 2) + koff);
            ldm_x4(al, alB + (uint32_t)(wm + arow) * (QK_STR * 2) + koff);
            uint32_t bh[2][4], bl[2][4];
            #pragma unroll
            for (int nb = 0; nb < 2; nb++) {
                ldm_x4(bh[nb], bhB + (uint32_t)(wn + nb * 16 + arow) * (QK_STR * 2) + koff);
                ldm_x4(bl[nb], blB + (uint32_t)(wn + nb * 16 + arow) * (QK_STR * 2) + koff);
            }
            #pragma unroll
            for (int nb = 0; nb < 2; nb++) {
                mma16816(acc[nb * 2 + 0], ah, bh[nb][0], bh[nb][2]);
                mma16816(acc[nb * 2 + 1], ah, bh[nb][1], bh[nb][3]);
                mma16816(acc[nb * 2 + 0], ah, bl[nb][0], bl[nb][2]);
                mma16816(acc[nb * 2 + 1], ah, bl[nb][1], bl[nb][3]);
                mma16816(acc[nb * 2 + 0], al, bh[nb][0], bh[nb][2]);
                mma16816(acc[nb * 2 + 1], al, bh[nb][1], bh[nb][3]);
            }
        }
    }

    const int gId = lane >> 2, tig = lane & 3;
    if (z == 2) {
        #pragma unroll
        for (int nf = 0; nf < 4; nf++) {
            int dkc = wn + nf * 8 + tig * 2;
            int m_lo = m0 + wm + gId;
            float b0v = bias[n0 + dkc], b1v = bias[n0 + dkc + 1];
            *(float2*)&g_v[((size_t)h * kS + m_lo) * 64 + dkc] =
                make_float2(acc[nf][0] + b0v, acc[nf][1] + b1v);
            *(float2*)&g_v[((size_t)h * kS + m_lo + 8) * 64 + dkc] =
                make_float2(acc[nf][2] + b0v, acc[nf][3] + b1v);
        }
    } else {
        __nv_bfloat16* dstc = (z == 0) ? g_qc : g_kc;
        const bool isq = (z == 0);
        #pragma unroll
        for (int nf = 0; nf < 4; nf++) {
            int dkc = wn + nf * 8 + tig * 2;
            float b0v = bias[n0 + dkc], b1v = bias[n0 + dkc + 1];
            #pragma unroll
            for (int half = 0; half < 2; half++) {
                int m = m0 + wm + gId + half * 8;
                float v0 = (acc[nf][half * 2 + 0] + b0v) * scale;
                float v1 = (acc[nf][half * 2 + 1] + b1v) * scale;
                uint32_t hh, ll;
                split2(v0, v1, hh, ll);
                size_t base = ((size_t)h * kS + m) * 192 + dkc;
                *(uint32_t*)&dstc[base] = hh;
                if (isq) { *(uint32_t*)&dstc[base + 64] = hh; *(uint32_t*)&dstc[base + 128] = ll; }
                else     { *(uint32_t*)&dstc[base + 64] = ll; *(uint32_t*)&dstc[base + 128] = hh; }
            }
        }
    }
}

// ================= Kernel 2: logits = Qcat @ Kcat^T (HMMA) =================
#define LG_ASTR 200
#define LG_SA   0
#define LG_SB   (128 * LG_ASTR * 2)
#define LG_SMEM (2 * 128 * LG_ASTR * 2)

__global__ __launch_bounds__(256, 1) void logits_kernel(float* __restrict__ logits)
{
    extern __shared__ char sm[];
    char* smA = sm + LG_SA;
    char* smB = sm + LG_SB;

    const int tid = threadIdx.x, wid = tid >> 5, lane = tid & 31;
    const int h = blockIdx.z;
    const int row0 = blockIdx.y * 128;
    const int col0 = blockIdx.x * 128;

    #pragma unroll
    for (int t = 0; t < 12; t++) {
        int i = tid + t * 256;
        int r = i / 24, cp = i % 24;
        *(uint4*)(smA + r * (LG_ASTR * 2) + cp * 16) =
            *(const uint4*)&g_qc[((size_t)h * kS + row0 + r) * 192 + cp * 8];
        *(uint4*)(smB + r * (LG_ASTR * 2) + cp * 16) =
            *(const uint4*)&g_kc[((size_t)h * kS + col0 + r) * 192 + cp * 8];
    }
    __syncthreads();

    const int wm = (wid & 3) * 32;
    const int wn = (wid >> 2) * 64;
    const uint32_t saBase = smem_u32(smA);
    const uint32_t sbBase = smem_u32(smB);

    float acc[2][8][4];
    #pragma unroll
    for (int i = 0; i < 2; i++)
        #pragma unroll
        for (int j = 0; j < 8; j++)
            #pragma unroll
            for (int q = 0; q < 4; q++) acc[i][j][q] = 0.f;

    const int arow = lane & 15, ak = (lane >> 4) * 8;
    #pragma unroll
    for (int ks = 0; ks < 12; ks++) {
        uint32_t a0[4], a1[4];
        ldm_x4(a0, saBase + (uint32_t)(wm + arow) * 400 + (uint32_t)(ks * 16 + ak) * 2);
        ldm_x4(a1, saBase + (uint32_t)(wm + 16 + arow) * 400 + (uint32_t)(ks * 16 + ak) * 2);
        uint32_t b[4][4];
        #pragma unroll
        for (int nb = 0; nb < 4; nb++)
            ldm_x4(b[nb], sbBase + (uint32_t)(wn + nb * 16 + arow) * 400 + (uint32_t)(ks * 16 + ak) * 2);
        #pragma unroll
        for (int nb = 0; nb < 4; nb++) {
            mma16816(acc[0][nb * 2 + 0], a0, b[nb][0], b[nb][2]);
            mma16816(acc[0][nb * 2 + 1], a0, b[nb][1], b[nb][3]);
            mma16816(acc[1][nb * 2 + 0], a1, b[nb][0], b[nb][2]);
            mma16816(acc[1][nb * 2 + 1], a1, b[nb][1], b[nb][3]);
        }
    }

    const int gId = lane >> 2, tig = lane & 3;
    #pragma unroll
    for (int mf = 0; mf < 2; mf++) {
        #pragma unroll
        for (int nf = 0; nf < 8; nf++) {
            int c = col0 + wn + nf * 8 + tig * 2;
            int r_lo = row0 + wm + mf * 16 + gId;
            float2 v0 = make_float2(acc[mf][nf][0], acc[mf][nf][1]);
            float2 v1 = make_float2(acc[mf][nf][2], acc[mf][nf][3]);
            *(float2*)&logits[((size_t)h * kS + r_lo) * kS + c]     = v0;
            *(float2*)&logits[((size_t)h * kS + r_lo + 8) * kS + c] = v1;
        }
    }
}

// ================= Kernel 3: entmax1.5, register-resident rows =================
__global__ __launch_bounds__(256, 1) void entmax_kernel(float* __restrict__ attn)
{
    const int h = blockIdx.y;
    const int tid = threadIdx.x, wid = tid >> 5, lane = tid & 31;
    const int row = blockIdx.x * 8 + wid;
    float4* rp = (float4*)(attn + ((size_t)(h * kS + row)) * kS);

    float4 v[24];
    #pragma unroll
    for (int i = 0; i < 24; i++) v[i] = rp[lane + i * 32];

    float mx = -3.4e38f;
    #pragma unroll
    for (int i = 0; i < 24; i++)
        mx = fmaxf(mx, fmaxf(fmaxf(v[i].x, v[i].y), fmaxf(v[i].z, v[i].w)));
    #pragma unroll
    for (int o = 16; o; o >>= 1) mx = fmaxf(mx, __shfl_xor_sync(0xffffffffu, mx, o));

    float sum = 0.f;
    #pragma unroll
    for (int i = 0; i < 24; i++) {
        v[i].x = (v[i].x - mx) * 0.5f; v[i].y = (v[i].y - mx) * 0.5f;
        v[i].z = (v[i].z - mx) * 0.5f; v[i].w = (v[i].w - mx) * 0.5f;
        sum += (v[i].x + v[i].y) + (v[i].z + v[i].w);
    }
    #pragma unroll
    for (int o = 16; o; o >>= 1) sum += __shfl_xor_sync(0xffffffffu, sum, o);

    float tau = fminf(fmaxf(sum * (1.0f / kS), -1.0f), -1e-6f);
    #pragma unroll 1
    for (int it = 0; it < NEWT; it++) {
        float g = 0.f, gp = 0.f;
        #pragma unroll
        for (int i = 0; i < 24; i++) {
            float t0 = fmaxf(v[i].x - tau, 0.f); g = fmaf(t0, t0, g); gp += t0;
            float t1 = fmaxf(v[i].y - tau, 0.f); g = fmaf(t1, t1, g); gp += t1;
            float t2 = fmaxf(v[i].z - tau, 0.f); g = fmaf(t2, t2, g); gp += t2;
            float t3 = fmaxf(v[i].w - tau, 0.f); g = fmaf(t3, t3, g); gp += t3;
        }
        #pragma unroll
        for (int o = 16; o; o >>= 1) {
            g  += __shfl_xor_sync(0xffffffffu, g, o);
            gp += __shfl_xor_sync(0xffffffffu, gp, o);
        }
        tau = tau + (g - 1.0f) / fmaxf(2.f * gp, 1e-20f);
        tau = fminf(fmaxf(tau, -1.0f), 0.0f);
    }

    #pragma unroll
    for (int i = 0; i < 24; i++) {
        float t;
        t = fmaxf(v[i].x - tau, 0.f); v[i].x = t * t;
        t = fmaxf(v[i].y - tau, 0.f); v[i].y = t * t;
        t = fmaxf(v[i].z - tau, 0.f); v[i].z = t * t;
        t = fmaxf(v[i].w - tau, 0.f); v[i].w = t * t;
        rp[lane + i * 32] = v[i];
    }
}

// ================= Kernel 4: ctx = P @ V (HMMA, double-buffered) =================
#define PV_STR   72
#define PV_STAGE (4 * 64 * PV_STR * 2)     // Ah|Al|Bh|Bl per stage = 36864 B
#define PV_SMEM  (2 * PV_STAGE)

__global__ __launch_bounds__(256, 2) void pv_kernel(const float* __restrict__ p)
{
    extern __shared__ char sm[];

    const int tid = threadIdx.x, wid = tid >> 5, lane = tid & 31;
    const int h = blockIdx.y;
    const int row0 = blockIdx.x * 64;

    float acc[4][4];
    #pragma unroll
    for (int j = 0; j < 4; j++)
        #pragma unroll
        for (int q = 0; q < 4; q++) acc[j][q] = 0.f;

    const int arow = lane & 15, ak = (lane >> 4) * 8;
    const int wm = (wid & 3) * 16;
    const int wn = (wid >> 2) * 32;

    const int pr0 = tid >> 4;
    const int pc4 = (tid & 15) * 4;
    const int vj  = tid & 63;
    const int vd0 = (tid >> 6) * 4;

    float4 pf_p[4], pf_v[4];

    // ---- prologue: load + convert chunk 0 into stage 0 ----
    {
        char* smAh = sm;
        char* smAl = sm + 64 * PV_STR * 2;
        char* smBh = sm + 2 * 64 * PV_STR * 2;
        char* smBl = sm + 3 * 64 * PV_STR * 2;
        #pragma unroll
        for (int t = 0; t < 4; t++) {
            pf_p[t] = *(const float4*)&p[((size_t)h * kS + row0 + pr0 + t * 16) * kS + pc4];
            pf_v[t] = *(const float4*)&g_v[((size_t)h * kS + vj) * 64 + vd0 + t * 16];
        }
        #pragma unroll
        for (int t = 0; t < 4; t++) {
            uint32_t h01, h23, l01, l23;
            split4(pf_p[t], h01, h23, l01, l23);
            uint32_t off = (uint32_t)(pr0 + t * 16) * (PV_STR * 2) + (uint32_t)pc4 * 2;
            *(uint2*)(smAh + off) = make_uint2(h01, h23);
            *(uint2*)(smAl + off) = make_uint2(l01, l23);
            float f[4] = {pf_v[t].x, pf_v[t].y, pf_v[t].z, pf_v[t].w};
            #pragma unroll
            for (int q = 0; q < 4; q++) {
                __nv_bfloat16 hb = __float2bfloat16(f[q]);
                __nv_bfloat16 lb = __float2bfloat16(f[q] - __bfloat162float(hb));
                *(__nv_bfloat16*)(smBh + (vd0 + t * 16 + q) * (PV_STR * 2) + vj * 2) = hb;
                *(__nv_bfloat16*)(smBl + (vd0 + t * 16 + q) * (PV_STR * 2) + vj * 2) = lb;
            }
        }
    }
    __syncthreads();

    #pragma unroll 1
    for (int c = 0; c < 48; c++) {
        char* rd = sm + (c & 1) * PV_STAGE;
        char* wr = sm + ((c + 1) & 1) * PV_STAGE;
        const uint32_t ahB = smem_u32(rd);
        const uint32_t alB = ahB + 64 * PV_STR * 2;
        const uint32_t bhB = ahB + 2 * 64 * PV_STR * 2;
        const uint32_t blB = ahB + 3 * 64 * PV_STR * 2;

        // prefetch next chunk into registers
        if (c < 47) {
            const int j0 = (c + 1) * 64;
            #pragma unroll
            for (int t = 0; t < 4; t++) {
                pf_p[t] = *(const float4*)&p[((size_t)h * kS + row0 + pr0 + t * 16) * kS + j0 + pc4];
                pf_v[t] = *(const float4*)&g_v[((size_t)h * kS + j0 + vj) * 64 + vd0 + t * 16];
            }
        }

        // compute chunk c from read stage
        #pragma unroll
        for (int ks = 0; ks < 4; ks++) {
            uint32_t koff = (uint32_t)(ks * 16 + ak) * 2;
            uint32_t ah[4], al[4];
            ldm_x4(ah, ahB + (uint32_t)(wm + arow) * (PV_STR * 2) + koff);
            ldm_x4(al, alB + (uint32_t)(wm + arow) * (PV_STR * 2) + koff);
            uint32_t bh[2][4], bl[2][4];
            #pragma unroll
            for (int nb = 0; nb < 2; nb++) {
                ldm_x4(bh[nb], bhB + (uint32_t)(wn + nb * 16 + arow) * (PV_STR * 2) + koff);
                ldm_x4(bl[nb], blB + (uint32_t)(wn + nb * 16 + arow) * (PV_STR * 2) + koff);
            }
            #pragma unroll
            for (int nb = 0; nb < 2; nb++) {
                mma16816(acc[nb * 2 + 0], ah, bh[nb][0], bh[nb][2]);
                mma16816(acc[nb * 2 + 1], ah, bh[nb][1], bh[nb][3]);
                mma16816(acc[nb * 2 + 0], ah, bl[nb][0], bl[nb][2]);
                mma16816(acc[nb * 2 + 1], ah, bl[nb][1], bl[nb][3]);
                mma16816(acc[nb * 2 + 0], al, bh[nb][0], bh[nb][2]);
                mma16816(acc[nb * 2 + 1], al, bh[nb][1], bh[nb][3]);
            }
        }

        // convert + store prefetched chunk into write stage
        if (c < 47) {
            char* smAh = wr;
            char* smAl = wr + 64 * PV_STR * 2;
            char* smBh = wr + 2 * 64 * PV_STR * 2;
            char* smBl = wr + 3 * 64 * PV_STR * 2;
            #pragma unroll
            for (int t = 0; t < 4; t++) {
                uint32_t h01, h23, l01, l23;
                split4(pf_p[t], h01, h23, l01, l23);
                uint32_t off = (uint32_t)(pr0 + t * 16) * (PV_STR * 2) + (uint32_t)pc4 * 2;
                *(uint2*)(smAh + off) = make_uint2(h01, h23);
                *(uint2*)(smAl + off) = make_uint2(l01, l23);
                float f[4] = {pf_v[t].x, pf_v[t].y, pf_v[t].z, pf_v[t].w};
                #pragma unroll
                for (int q = 0; q < 4; q++) {
                    __nv_bfloat16 hb = __float2bfloat16(f[q]);
                    __nv_bfloat16 lb = __float2bfloat16(f[q] - __bfloat162float(hb));
                    *(__nv_bfloat16*)(smBh + (vd0 + t * 16 + q) * (PV_STR * 2) + vj * 2) = hb;
                    *(__nv_bfloat16*)(smBl + (vd0 + t * 16 + q) * (PV_STR * 2) + vj * 2) = lb;
                }
            }
        }
        __syncthreads();
    }

    const int gId = lane >> 2, tig = lane & 3;
    #pragma unroll
    for (int f = 0; f < 4; f++) {
        int cc = wn + (f >> 1) * 16 + (f & 1) * 8 + tig * 2;
        int r_lo = row0 + wm + gId;
        *(float2*)&g_ctx[(size_t)r_lo * kD + h * 64 + cc] =
            make_float2(acc[f][0], acc[f][1]);
        *(float2*)&g_ctx[(size_t)(r_lo + 8) * kD + h * 64 + cc] =
            make_float2(acc[f][2], acc[f][3]);
    }
}

// ================= Kernel 5: Wo GEMM + residual + LN =================
__global__ __launch_bounds__(256) void out_kernel(
    const float* __restrict__ x,
    const float* __restrict__ Wo, const float* __restrict__ bo,
    const float* __restrict__ gamma, const float* __restrict__ beta,
    float* __restrict__ out)
{
    __shared__ float sC[16 * kD];

    const int m0  = blockIdx.x * 16;
    const int tid = threadIdx.x;

    for (int i = tid; i < 2048; i += 256)
        ((float4*)sC)[i] = ((const float4*)&g_ctx[(size_t)m0 * kD])[i];
    __syncthreads();

    const int n0 = tid, n1 = tid + 256;
    float acc0[16], acc1[16];
    #pragma unroll
    for (int r = 0; r < 16; r++) { acc0[r] = 0.f; acc1[r] = 0.f; }

    for (int k = 0; k < kD; k += 4) {
        float w0[4], w1[4];
        #pragma unroll
        for (int kk = 0; kk < 4; kk++) {
            w0[kk] = Wo[(size_t)(k + kk) * kD + n0];
            w1[kk] = Wo[(size_t)(k + kk) * kD + n1];
        }
        #pragma unroll
        for (int r = 0; r < 16; r++) {
            float4 cv4 = *(const float4*)&sC[r * kD + k];
            float cv[4] = {cv4.x, cv4.y, cv4.z, cv4.w};
            #pragma unroll
            for (int kk = 0; kk < 4; kk++) {
                acc0[r] = fmaf(cv[kk], w0[kk], acc0[r]);
                acc1[r] = fmaf(cv[kk], w1[kk], acc1[r]);
            }
        }
    }
    __syncthreads();

    const float b0v = bo[n0], b1v = bo[n1];
    #pragma unroll
    for (int r = 0; r < 16; r++) {
        sC[r * kD + n0] = acc0[r] + b0v + x[(size_t)(m0 + r) * kD + n0];
        sC[r * kD + n1] = acc1[r] + b1v + x[(size_t)(m0 + r) * kD + n1];
    }
    __syncthreads();

    const int wid = tid >> 5, lane = tid & 31;
    #pragma unroll 1
    for (int rr = 0; rr < 2; rr++) {
        int r = wid * 2 + rr;
        float s = 0.f, ss = 0.f;
        for (int i = lane; i < kD; i += 32) {
            float v = sC[r * kD + i];
            s += v; ss = fmaf(v, v, ss);
        }
        #pragma unroll
        for (int o = 16; o; o >>= 1) {
            s  += __shfl_xor_sync(0xffffffffu, s, o);
            ss += __shfl_xor_sync(0xffffffffu, ss, o);
        }
        float mu  = s * (1.f / kD);
        float var = ss * (1.f / kD) - mu * mu;
        float inv = rsqrtf(var + 1e-6f);
        for (int i = lane; i < kD; i += 32) {
            float v = sC[r * kD + i];
            out[(size_t)(m0 + r) * kD + i] = (v - mu) * inv * gamma[i] + beta[i];
        }
    }
}

// ================= launcher =================
extern "C" void kernel_launch(void* const* d_in, const int* in_sizes, int n_in,
                              void* d_out, int out_size)
{
    const float* x     = (const float*)d_in[0];
    const float* Wq    = (const float*)d_in[1];
    const float* bq    = (const float*)d_in[2];
    const float* Wk    = (const float*)d_in[3];
    const float* bk    = (const float*)d_in[4];
    const float* Wv    = (const float*)d_in[5];
    const float* bv    = (const float*)d_in[6];
    const float* Wo    = (const float*)d_in[7];
    const float* bo    = (const float*)d_in[8];
    const float* gamma = (const float*)d_in[9];
    const float* beta  = (const float*)d_in[10];

    float* out  = (float*)d_out;
    float* attn = out + (size_t)kS * kD;

    cudaFuncSetAttribute(logits_kernel, cudaFuncAttributeMaxDynamicSharedMemorySize, LG_SMEM);
    cudaFuncSetAttribute(pv_kernel,     cudaFuncAttributeMaxDynamicSharedMemorySize, PV_SMEM);

    xsplit_kernel<<<kS * kD / 4 / 256, 256>>>(x);
    wsplit_kernel<<<dim3(kD * kD / 4 / 256, 3), 256>>>(Wq, Wk, Wv);
    qkv_kernel<<<dim3(48, 8, 3), 256>>>(bq, bk, bv);
    logits_kernel<<<dim3(24, 24, 8), 256, LG_SMEM>>>(attn);
    entmax_kernel<<<dim3(kS / 8, kH), 256>>>(attn);
    pv_kernel<<<dim3(48, 8), 256, PV_SMEM>>>(attn);
    out_kernel<<<kS / 16, 256>>>(x, Wo, bo, gamma, beta, out);
}

// round 12
// speedup vs baseline: 1.3089x; 1.2127x over previous
#include <cuda_runtime.h>
#include <cuda_bf16.h>
#include <cstdint>

#define kS 3072
#define kD 512
#define kH 8
#define NEWT 6

__device__ __nv_bfloat16 g_qc[(size_t)kH * kS * 192];
__device__ __nv_bfloat16 g_kc[(size_t)kH * kS * 192];
__device__ float g_v[(size_t)kH * kS * 64];
__device__ float g_ctx[(size_t)kS * kD];
__device__ __nv_bfloat16 g_xh[(size_t)kS * kD];
__device__ __nv_bfloat16 g_xl[(size_t)kS * kD];
__device__ __nv_bfloat16 g_wth[(size_t)3 * kD * kD];   // [z][n][k]
__device__ __nv_bfloat16 g_wtl[(size_t)3 * kD * kD];
__device__ __nv_bfloat16 g_vth[(size_t)kH * 64 * kS];  // [h][dv][j]
__device__ __nv_bfloat16 g_vtl[(size_t)kH * 64 * kS];

// ======================= helpers =======================
__device__ __forceinline__ uint32_t smem_u32(const void* p) {
    uint32_t a;
    asm("{ .reg .u64 t; cvta.to.shared.u64 t, %1; cvt.u32.u64 %0, t; }" : "=r"(a) : "l"(p));
    return a;
}
__device__ __forceinline__ void ldm_x4(uint32_t* r, uint32_t addr) {
    asm volatile("ldmatrix.sync.aligned.m8n8.x4.shared.b16 {%0,%1,%2,%3}, [%4];"
                 : "=r"(r[0]), "=r"(r[1]), "=r"(r[2]), "=r"(r[3]) : "r"(addr));
}
__device__ __forceinline__ void mma16816(float* c, const uint32_t* a, uint32_t b0, uint32_t b1) {
    asm volatile("mma.sync.aligned.m16n8k16.row.col.f32.bf16.bf16.f32 "
                 "{%0,%1,%2,%3}, {%4,%5,%6,%7}, {%8,%9}, {%0,%1,%2,%3};"
                 : "+f"(c[0]), "+f"(c[1]), "+f"(c[2]), "+f"(c[3])
                 : "r"(a[0]), "r"(a[1]), "r"(a[2]), "r"(a[3]), "r"(b0), "r"(b1));
}
#define CP_ASYNC16(saddr, gptr) \
    asm volatile("cp.async.cg.shared.global [%0], [%1], 16;" :: "r"(saddr), "l"(gptr))
#define CP_COMMIT() asm volatile("cp.async.commit_group;" ::: "memory")
#define CP_WAIT1()  asm volatile("cp.async.wait_group 1;" ::: "memory")
#define CP_WAIT0()  asm volatile("cp.async.wait_group 0;" ::: "memory")

__device__ __forceinline__ void split4(float4 f, uint32_t& h01, uint32_t& h23,
                                       uint32_t& l01, uint32_t& l23) {
    __nv_bfloat16 h0 = __float2bfloat16(f.x);
    __nv_bfloat16 h1 = __float2bfloat16(f.y);
    __nv_bfloat16 h2 = __float2bfloat16(f.z);
    __nv_bfloat16 h3 = __float2bfloat16(f.w);
    __nv_bfloat16 l0 = __float2bfloat16(f.x - __bfloat162float(h0));
    __nv_bfloat16 l1 = __float2bfloat16(f.y - __bfloat162float(h1));
    __nv_bfloat16 l2 = __float2bfloat16(f.z - __bfloat162float(h2));
    __nv_bfloat16 l3 = __float2bfloat16(f.w - __bfloat162float(h3));
    h01 = ((uint32_t)__bfloat16_as_ushort(h1) << 16) | __bfloat16_as_ushort(h0);
    h23 = ((uint32_t)__bfloat16_as_ushort(h3) << 16) | __bfloat16_as_ushort(h2);
    l01 = ((uint32_t)__bfloat16_as_ushort(l1) << 16) | __bfloat16_as_ushort(l0);
    l23 = ((uint32_t)__bfloat16_as_ushort(l3) << 16) | __bfloat16_as_ushort(l2);
}
__device__ __forceinline__ void split2(float a, float b, uint32_t& hh, uint32_t& ll) {
    __nv_bfloat16 h0 = __float2bfloat16(a);
    __nv_bfloat16 h1 = __float2bfloat16(b);
    __nv_bfloat16 l0 = __float2bfloat16(a - __bfloat162float(h0));
    __nv_bfloat16 l1 = __float2bfloat16(b - __bfloat162float(h1));
    hh = ((uint32_t)__bfloat16_as_ushort(h1) << 16) | __bfloat16_as_ushort(h0);
    ll = ((uint32_t)__bfloat16_as_ushort(l1) << 16) | __bfloat16_as_ushort(l0);
}

// ================= Prepass A: x -> hi/lo bf16 =================
__global__ __launch_bounds__(256) void xsplit_kernel(const float* __restrict__ x)
{
    int i = blockIdx.x * 256 + threadIdx.x;
    float4 v = ((const float4*)x)[i];
    uint32_t h01, h23, l01, l23;
    split4(v, h01, h23, l01, l23);
    ((uint2*)g_xh)[i] = make_uint2(h01, h23);
    ((uint2*)g_xl)[i] = make_uint2(l01, l23);
}

// ================= Prepass B: W -> transposed hi/lo bf16 =================
__global__ __launch_bounds__(256) void wsplit_kernel(
    const float* __restrict__ Wq, const float* __restrict__ Wk, const float* __restrict__ Wv)
{
    const int z = blockIdx.y;
    const float* W = (z == 0) ? Wq : (z == 1) ? Wk : Wv;
    int i = blockIdx.x * 256 + threadIdx.x;
    int n = i >> 7;
    int kq = (i & 127) * 4;
    float4 v;
    v.x = W[(size_t)(kq + 0) * kD + n];
    v.y = W[(size_t)(kq + 1) * kD + n];
    v.z = W[(size_t)(kq + 2) * kD + n];
    v.w = W[(size_t)(kq + 3) * kD + n];
    uint32_t h01, h23, l01, l23;
    split4(v, h01, h23, l01, l23);
    size_t o = ((size_t)z * kD + n) * kD + kq;
    *(uint2*)&g_wth[o] = make_uint2(h01, h23);
    *(uint2*)&g_wtl[o] = make_uint2(l01, l23);
}

// ================= Prepass C: V -> transposed hi/lo bf16 [h][dv][j] =================
__global__ __launch_bounds__(256) void vsplit_kernel()
{
    const int h = blockIdx.y;
    const int dv = blockIdx.x / 3;
    const int j = (blockIdx.x % 3) * 1024 + threadIdx.x * 4;
    float4 f;
    f.x = g_v[((size_t)h * kS + j + 0) * 64 + dv];
    f.y = g_v[((size_t)h * kS + j + 1) * 64 + dv];
    f.z = g_v[((size_t)h * kS + j + 2) * 64 + dv];
    f.w = g_v[((size_t)h * kS + j + 3) * 64 + dv];
    uint32_t h01, h23, l01, l23;
    split4(f, h01, h23, l01, l23);
    size_t o = ((size_t)h * 64 + dv) * kS + j;
    *(uint2*)&g_vth[o] = make_uint2(h01, h23);
    *(uint2*)&g_vtl[o] = make_uint2(l01, l23);
}

// ================= Kernel 1: QKV projections (HMMA) =================
#define QK_STR 72
__global__ __launch_bounds__(256) void qkv_kernel(
    const float* __restrict__ bq, const float* __restrict__ bk, const float* __restrict__ bv)
{
    __shared__ __align__(16) char s[4 * 64 * QK_STR * 2];
    char* sAh = s;
    char* sAl = s + 64 * QK_STR * 2;
    char* sBh = s + 2 * 64 * QK_STR * 2;
    char* sBl = s + 3 * 64 * QK_STR * 2;

    const int m0 = blockIdx.x * 64;
    const int h  = blockIdx.y;
    const int z  = blockIdx.z;
    const int n0 = h * 64;
    const float* bias = (z == 0) ? bq : (z == 1) ? bk : bv;
    const float scale = (z == 0) ? 0.125f : 1.0f;

    const int tid = threadIdx.x, wid = tid >> 5, lane = tid & 31;
    const uint32_t ahB = smem_u32(sAh), alB = smem_u32(sAl);
    const uint32_t bhB = smem_u32(sBh), blB = smem_u32(sBl);

    const int wm = (wid & 3) * 16;
    const int wn = (wid >> 2) * 32;
    const int arow = lane & 15, ak = (lane >> 4) * 8;

    float acc[4][4];
    #pragma unroll
    for (int j = 0; j < 4; j++)
        #pragma unroll
        for (int q = 0; q < 4; q++) acc[j][q] = 0.f;

    #pragma unroll 1
    for (int k0 = 0; k0 < kD; k0 += 64) {
        __syncthreads();
        #pragma unroll
        for (int t = 0; t < 4; t++) {
            int i = tid + t * 256;
            int r = i >> 4, c4 = (i & 15) * 4;
            uint32_t off = (uint32_t)r * (QK_STR * 2) + (uint32_t)c4 * 2;
            size_t ax = (size_t)(m0 + r) * kD + k0 + c4;
            *(uint2*)(sAh + off) = *(const uint2*)&g_xh[ax];
            *(uint2*)(sAl + off) = *(const uint2*)&g_xl[ax];
            size_t bx = ((size_t)z * kD + n0 + r) * kD + k0 + c4;
            *(uint2*)(sBh + off) = *(const uint2*)&g_wth[bx];
            *(uint2*)(sBl + off) = *(const uint2*)&g_wtl[bx];
        }
        __syncthreads();

        #pragma unroll
        for (int ks = 0; ks < 4; ks++) {
            uint32_t koff = (uint32_t)(ks * 16 + ak) * 2;
            uint32_t ah[4], al[4];
            ldm_x4(ah, ahB + (uint32_t)(wm + arow) * (QK_STR * 2) + koff);
            ldm_x4(al, alB + (uint32_t)(wm + arow) * (QK_STR * 2) + koff);
            uint32_t bh[2][4], bl[2][4];
            #pragma unroll
            for (int nb = 0; nb < 2; nb++) {
                ldm_x4(bh[nb], bhB + (uint32_t)(wn + nb * 16 + arow) * (QK_STR * 2) + koff);
                ldm_x4(bl[nb], blB + (uint32_t)(wn + nb * 16 + arow) * (QK_STR * 2) + koff);
            }
            #pragma unroll
            for (int nb = 0; nb < 2; nb++) {
                mma16816(acc[nb * 2 + 0], ah, bh[nb][0], bh[nb][2]);
                mma16816(acc[nb * 2 + 1], ah, bh[nb][1], bh[nb][3]);
                mma16816(acc[nb * 2 + 0], ah, bl[nb][0], bl[nb][2]);
                mma16816(acc[nb * 2 + 1], ah, bl[nb][1], bl[nb][3]);
                mma16816(acc[nb * 2 + 0], al, bh[nb][0], bh[nb][2]);
                mma16816(acc[nb * 2 + 1], al, bh[nb][1], bh[nb][3]);
            }
        }
    }

    const int gId = lane >> 2, tig = lane & 3;
    if (z == 2) {
        #pragma unroll
        for (int nf = 0; nf < 4; nf++) {
            int dkc = wn + nf * 8 + tig * 2;
            int m_lo = m0 + wm + gId;
            float b0v = bias[n0 + dkc], b1v = bias[n0 + dkc + 1];
            *(float2*)&g_v[((size_t)h * kS + m_lo) * 64 + dkc] =
                make_float2(acc[nf][0] + b0v, acc[nf][1] + b1v);
            *(float2*)&g_v[((size_t)h * kS + m_lo + 8) * 64 + dkc] =
                make_float2(acc[nf][2] + b0v, acc[nf][3] + b1v);
        }
    } else {
        __nv_bfloat16* dstc = (z == 0) ? g_qc : g_kc;
        const bool isq = (z == 0);
        #pragma unroll
        for (int nf = 0; nf < 4; nf++) {
            int dkc = wn + nf * 8 + tig * 2;
            float b0v = bias[n0 + dkc], b1v = bias[n0 + dkc + 1];
            #pragma unroll
            for (int half = 0; half < 2; half++) {
                int m = m0 + wm + gId + half * 8;
                float v0 = (acc[nf][half * 2 + 0] + b0v) * scale;
                float v1 = (acc[nf][half * 2 + 1] + b1v) * scale;
                uint32_t hh, ll;
                split2(v0, v1, hh, ll);
                size_t base = ((size_t)h * kS + m) * 192 + dkc;
                *(uint32_t*)&dstc[base] = hh;
                if (isq) { *(uint32_t*)&dstc[base + 64] = hh; *(uint32_t*)&dstc[base + 128] = ll; }
                else     { *(uint32_t*)&dstc[base + 64] = ll; *(uint32_t*)&dstc[base + 128] = hh; }
            }
        }
    }
}

// ================= Kernel 2: logits (HMMA, cp.async 2-stage pipeline) =================
#define LG_STR   208
#define LG_STAGE (2 * 128 * LG_STR)     // A+B per stage = 53248
#define LG_SMEM  (2 * LG_STAGE)         // 106496

__global__ __launch_bounds__(256, 2) void logits_kernel(float* __restrict__ logits)
{
    extern __shared__ char sm[];
    const int tid = threadIdx.x, wid = tid >> 5, lane = tid & 31;
    const int h = blockIdx.z;
    const int row0 = blockIdx.y * 128;
    const int col0 = blockIdx.x * 128;
    const uint32_t smBase = smem_u32(sm);

    // issue both K-stages (96 cols each) via cp.async
    #pragma unroll
    for (int s = 0; s < 2; s++) {
        const int k0 = s * 96;
        const uint32_t stA = smBase + s * LG_STAGE;
        const uint32_t stB = stA + 128 * LG_STR;
        #pragma unroll
        for (int t = 0; t < 6; t++) {
            int i = tid + t * 256;          // 0..1535
            int r = i / 12, cp = i % 12;
            CP_ASYNC16(stA + (uint32_t)r * LG_STR + (uint32_t)cp * 16,
                       &g_qc[((size_t)h * kS + row0 + r) * 192 + k0 + cp * 8]);
            CP_ASYNC16(stB + (uint32_t)r * LG_STR + (uint32_t)cp * 16,
                       &g_kc[((size_t)h * kS + col0 + r) * 192 + k0 + cp * 8]);
        }
        CP_COMMIT();
    }

    const int wm = (wid & 3) * 32;
    const int wn = (wid >> 2) * 64;
    const int arow = lane & 15, ak = (lane >> 4) * 8;

    float acc[2][8][4];
    #pragma unroll
    for (int i = 0; i < 2; i++)
        #pragma unroll
        for (int j = 0; j < 8; j++)
            #pragma unroll
            for (int q = 0; q < 4; q++) acc[i][j][q] = 0.f;

    #pragma unroll
    for (int s = 0; s < 2; s++) {
        if (s == 0) { CP_WAIT1(); } else { CP_WAIT0(); }
        __syncthreads();
        const uint32_t saBase = smBase + s * LG_STAGE;
        const uint32_t sbBase = saBase + 128 * LG_STR;
        #pragma unroll
        for (int ks = 0; ks < 6; ks++) {
            uint32_t koff = (uint32_t)(ks * 16 + ak) * 2;
            uint32_t a0[4], a1[4];
            ldm_x4(a0, saBase + (uint32_t)(wm + arow) * LG_STR + koff);
            ldm_x4(a1, saBase + (uint32_t)(wm + 16 + arow) * LG_STR + koff);
            uint32_t b[4][4];
            #pragma unroll
            for (int nb = 0; nb < 4; nb++)
                ldm_x4(b[nb], sbBase + (uint32_t)(wn + nb * 16 + arow) * LG_STR + koff);
            #pragma unroll
            for (int nb = 0; nb < 4; nb++) {
                mma16816(acc[0][nb * 2 + 0], a0, b[nb][0], b[nb][2]);
                mma16816(acc[0][nb * 2 + 1], a0, b[nb][1], b[nb][3]);
                mma16816(acc[1][nb * 2 + 0], a1, b[nb][0], b[nb][2]);
                mma16816(acc[1][nb * 2 + 1], a1, b[nb][1], b[nb][3]);
            }
        }
        if (s == 0) __syncthreads();
    }

    const int gId = lane >> 2, tig = lane & 3;
    #pragma unroll
    for (int mf = 0; mf < 2; mf++) {
        #pragma unroll
        for (int nf = 0; nf < 8; nf++) {
            int c = col0 + wn + nf * 8 + tig * 2;
            int r_lo = row0 + wm + mf * 16 + gId;
            *(float2*)&logits[((size_t)h * kS + r_lo) * kS + c] =
                make_float2(acc[mf][nf][0], acc[mf][nf][1]);
            *(float2*)&logits[((size_t)h * kS + r_lo + 8) * kS + c] =
                make_float2(acc[mf][nf][2], acc[mf][nf][3]);
        }
    }
}

// ================= Kernel 3: entmax1.5, register-resident rows =================
__global__ __launch_bounds__(256, 1) void entmax_kernel(float* __restrict__ attn)
{
    const int h = blockIdx.y;
    const int tid = threadIdx.x, wid = tid >> 5, lane = tid & 31;
    const int row = blockIdx.x * 8 + wid;
    float4* rp = (float4*)(attn + ((size_t)(h * kS + row)) * kS);

    float4 v[24];
    #pragma unroll
    for (int i = 0; i < 24; i++) v[i] = rp[lane + i * 32];

    float mx = -3.4e38f;
    #pragma unroll
    for (int i = 0; i < 24; i++)
        mx = fmaxf(mx, fmaxf(fmaxf(v[i].x, v[i].y), fmaxf(v[i].z, v[i].w)));
    #pragma unroll
    for (int o = 16; o; o >>= 1) mx = fmaxf(mx, __shfl_xor_sync(0xffffffffu, mx, o));

    float sum = 0.f;
    #pragma unroll
    for (int i = 0; i < 24; i++) {
        v[i].x = (v[i].x - mx) * 0.5f; v[i].y = (v[i].y - mx) * 0.5f;
        v[i].z = (v[i].z - mx) * 0.5f; v[i].w = (v[i].w - mx) * 0.5f;
        sum += (v[i].x + v[i].y) + (v[i].z + v[i].w);
    }
    #pragma unroll
    for (int o = 16; o; o >>= 1) sum += __shfl_xor_sync(0xffffffffu, sum, o);

    float tau = fminf(fmaxf(sum * (1.0f / kS), -1.0f), -1e-6f);
    #pragma unroll 1
    for (int it = 0; it < NEWT; it++) {
        float g = 0.f, gp = 0.f;
        #pragma unroll
        for (int i = 0; i < 24; i++) {
            float t0 = fmaxf(v[i].x - tau, 0.f); g = fmaf(t0, t0, g); gp += t0;
            float t1 = fmaxf(v[i].y - tau, 0.f); g = fmaf(t1, t1, g); gp += t1;
            float t2 = fmaxf(v[i].z - tau, 0.f); g = fmaf(t2, t2, g); gp += t2;
            float t3 = fmaxf(v[i].w - tau, 0.f); g = fmaf(t3, t3, g); gp += t3;
        }
        #pragma unroll
        for (int o = 16; o; o >>= 1) {
            g  += __shfl_xor_sync(0xffffffffu, g, o);
            gp += __shfl_xor_sync(0xffffffffu, gp, o);
        }
        tau = tau + (g - 1.0f) / fmaxf(2.f * gp, 1e-20f);
        tau = fminf(fmaxf(tau, -1.0f), 0.0f);
    }

    #pragma unroll
    for (int i = 0; i < 24; i++) {
        float t;
        t = fmaxf(v[i].x - tau, 0.f); v[i].x = t * t;
        t = fmaxf(v[i].y - tau, 0.f); v[i].y = t * t;
        t = fmaxf(v[i].z - tau, 0.f); v[i].z = t * t;
        t = fmaxf(v[i].w - tau, 0.f); v[i].w = t * t;
        rp[lane + i * 32] = v[i];
    }
}

// ================= Kernel 4: ctx = P @ V (HMMA, double-buffered, prepacked V) =================
#define PV_STR   72
#define PV_STAGE (4 * 64 * PV_STR * 2)     // Ah|Al|Bh|Bl per stage = 36864 B
#define PV_SMEM  (2 * PV_STAGE)

__global__ __launch_bounds__(256, 2) void pv_kernel(const float* __restrict__ p)
{
    extern __shared__ char sm[];

    const int tid = threadIdx.x, wid = tid >> 5, lane = tid & 31;
    const int h = blockIdx.y;
    const int row0 = blockIdx.x * 64;

    float acc[4][4];
    #pragma unroll
    for (int j = 0; j < 4; j++)
        #pragma unroll
        for (int q = 0; q < 4; q++) acc[j][q] = 0.f;

    const int arow = lane & 15, ak = (lane >> 4) * 8;
    const int wm = (wid & 3) * 16;
    const int wn = (wid >> 2) * 32;

    const int pr0 = tid >> 4;            // p row base
    const int pc4 = (tid & 15) * 4;      // p col in chunk
    const int vdv = tid >> 4;            // v dv base (+16 per t)
    const int vj  = (tid & 15) * 4;      // v j in chunk

    float4 pf_p[4];
    uint2  pf_vh[4], pf_vl[4];

    // ---- prologue: load + fill stage 0 ----
    {
        char* smAh = sm;
        char* smAl = sm + 64 * PV_STR * 2;
        char* smBh = sm + 2 * 64 * PV_STR * 2;
        char* smBl = sm + 3 * 64 * PV_STR * 2;
        #pragma unroll
        for (int t = 0; t < 4; t++) {
            pf_p[t]  = *(const float4*)&p[((size_t)h * kS + row0 + pr0 + t * 16) * kS + pc4];
            pf_vh[t] = *(const uint2*)&g_vth[((size_t)h * 64 + vdv + t * 16) * kS + vj];
            pf_vl[t] = *(const uint2*)&g_vtl[((size_t)h * 64 + vdv + t * 16) * kS + vj];
        }
        #pragma unroll
        for (int t = 0; t < 4; t++) {
            uint32_t h01, h23, l01, l23;
            split4(pf_p[t], h01, h23, l01, l23);
            uint32_t offA = (uint32_t)(pr0 + t * 16) * (PV_STR * 2) + (uint32_t)pc4 * 2;
            *(uint2*)(smAh + offA) = make_uint2(h01, h23);
            *(uint2*)(smAl + offA) = make_uint2(l01, l23);
            uint32_t offB = (uint32_t)(vdv + t * 16) * (PV_STR * 2) + (uint32_t)vj * 2;
            *(uint2*)(smBh + offB) = pf_vh[t];
            *(uint2*)(smBl + offB) = pf_vl[t];
        }
    }
    __syncthreads();

    #pragma unroll 1
    for (int c = 0; c < 48; c++) {
        char* rd = sm + (c & 1) * PV_STAGE;
        char* wr = sm + ((c + 1) & 1) * PV_STAGE;
        const uint32_t ahB = smem_u32(rd);
        const uint32_t alB = ahB + 64 * PV_STR * 2;
        const uint32_t bhB = ahB + 2 * 64 * PV_STR * 2;
        const uint32_t blB = ahB + 3 * 64 * PV_STR * 2;

        if (c < 47) {
            const int j0 = (c + 1) * 64;
            #pragma unroll
            for (int t = 0; t < 4; t++) {
                pf_p[t]  = *(const float4*)&p[((size_t)h * kS + row0 + pr0 + t * 16) * kS + j0 + pc4];
                pf_vh[t] = *(const uint2*)&g_vth[((size_t)h * 64 + vdv + t * 16) * kS + j0 + vj];
                pf_vl[t] = *(const uint2*)&g_vtl[((size_t)h * 64 + vdv + t * 16) * kS + j0 + vj];
            }
        }

        #pragma unroll
        for (int ks = 0; ks < 4; ks++) {
            uint32_t koff = (uint32_t)(ks * 16 + ak) * 2;
            uint32_t ah[4], al[4];
            ldm_x4(ah, ahB + (uint32_t)(wm + arow) * (PV_STR * 2) + koff);
            ldm_x4(al, alB + (uint32_t)(wm + arow) * (PV_STR * 2) + koff);
            uint32_t bh[2][4], bl[2][4];
            #pragma unroll
            for (int nb = 0; nb < 2; nb++) {
                ldm_x4(bh[nb], bhB + (uint32_t)(wn + nb * 16 + arow) * (PV_STR * 2) + koff);
                ldm_x4(bl[nb], blB + (uint32_t)(wn + nb * 16 + arow) * (PV_STR * 2) + koff);
            }
            #pragma unroll
            for (int nb = 0; nb < 2; nb++) {
                mma16816(acc[nb * 2 + 0], ah, bh[nb][0], bh[nb][2]);
                mma16816(acc[nb * 2 + 1], ah, bh[nb][1], bh[nb][3]);
                mma16816(acc[nb * 2 + 0], ah, bl[nb][0], bl[nb][2]);
                mma16816(acc[nb * 2 + 1], ah, bl[nb][1], bl[nb][3]);
                mma16816(acc[nb * 2 + 0], al, bh[nb][0], bh[nb][2]);
                mma16816(acc[nb * 2 + 1], al, bh[nb][1], bh[nb][3]);
            }
        }

        if (c < 47) {
            char* smAh = wr;
            char* smAl = wr + 64 * PV_STR * 2;
            char* smBh = wr + 2 * 64 * PV_STR * 2;
            char* smBl = wr + 3 * 64 * PV_STR * 2;
            #pragma unroll
            for (int t = 0; t < 4; t++) {
                uint32_t h01, h23, l01, l23;
                split4(pf_p[t], h01, h23, l01, l23);
                uint32_t offA = (uint32_t)(pr0 + t * 16) * (PV_STR * 2) + (uint32_t)pc4 * 2;
                *(uint2*)(smAh + offA) = make_uint2(h01, h23);
                *(uint2*)(smAl + offA) = make_uint2(l01, l23);
                uint32_t offB = (uint32_t)(vdv + t * 16) * (PV_STR * 2) + (uint32_t)vj * 2;
                *(uint2*)(smBh + offB) = pf_vh[t];
                *(uint2*)(smBl + offB) = pf_vl[t];
            }
        }
        __syncthreads();
    }

    const int gId = lane >> 2, tig = lane & 3;
    #pragma unroll
    for (int f = 0; f < 4; f++) {
        int cc = wn + (f >> 1) * 16 + (f & 1) * 8 + tig * 2;
        int r_lo = row0 + wm + gId;
        *(float2*)&g_ctx[(size_t)r_lo * kD + h * 64 + cc] =
            make_float2(acc[f][0], acc[f][1]);
        *(float2*)&g_ctx[(size_t)(r_lo + 8) * kD + h * 64 + cc] =
            make_float2(acc[f][2], acc[f][3]);
    }
}

// ================= Kernel 5: Wo GEMM + residual + LN =================
__global__ __launch_bounds__(256) void out_kernel(
    const float* __restrict__ x,
    const float* __restrict__ Wo, const float* __restrict__ bo,
    const float* __restrict__ gamma, const float* __restrict__ beta,
    float* __restrict__ out)
{
    __shared__ float sC[16 * kD];

    const int m0  = blockIdx.x * 16;
    const int tid = threadIdx.x;

    for (int i = tid; i < 2048; i += 256)
        ((float4*)sC)[i] = ((const float4*)&g_ctx[(size_t)m0 * kD])[i];
    __syncthreads();

    const int n0 = tid, n1 = tid + 256;
    float acc0[16], acc1[16];
    #pragma unroll
    for (int r = 0; r < 16; r++) { acc0[r] = 0.f; acc1[r] = 0.f; }

    for (int k = 0; k < kD; k += 4) {
        float w0[4], w1[4];
        #pragma unroll
        for (int kk = 0; kk < 4; kk++) {
            w0[kk] = Wo[(size_t)(k + kk) * kD + n0];
            w1[kk] = Wo[(size_t)(k + kk) * kD + n1];
        }
        #pragma unroll
        for (int r = 0; r < 16; r++) {
            float4 cv4 = *(const float4*)&sC[r * kD + k];
            float cv[4] = {cv4.x, cv4.y, cv4.z, cv4.w};
            #pragma unroll
            for (int kk = 0; kk < 4; kk++) {
                acc0[r] = fmaf(cv[kk], w0[kk], acc0[r]);
                acc1[r] = fmaf(cv[kk], w1[kk], acc1[r]);
            }
        }
    }
    __syncthreads();

    const float b0v = bo[n0], b1v = bo[n1];
    #pragma unroll
    for (int r = 0; r < 16; r++) {
        sC[r * kD + n0] = acc0[r] + b0v + x[(size_t)(m0 + r) * kD + n0];
        sC[r * kD + n1] = acc1[r] + b1v + x[(size_t)(m0 + r) * kD + n1];
    }
    __syncthreads();

    const int wid = tid >> 5, lane = tid & 31;
    #pragma unroll 1
    for (int rr = 0; rr < 2; rr++) {
        int r = wid * 2 + rr;
        float s = 0.f, ss = 0.f;
        for (int i = lane; i < kD; i += 32) {
            float v = sC[r * kD + i];
            s += v; ss = fmaf(v, v, ss);
        }
        #pragma unroll
        for (int o = 16; o; o >>= 1) {
            s  += __shfl_xor_sync(0xffffffffu, s, o);
            ss += __shfl_xor_sync(0xffffffffu, ss, o);
        }
        float mu  = s * (1.f / kD);
        float var = ss * (1.f / kD) - mu * mu;
        float inv = rsqrtf(var + 1e-6f);
        for (int i = lane; i < kD; i += 32) {
            float v = sC[r * kD + i];
            out[(size_t)(m0 + r) * kD + i] = (v - mu) * inv * gamma[i] + beta[i];
        }
    }
}

// ================= launcher =================
extern "C" void kernel_launch(void* const* d_in, const int* in_sizes, int n_in,
                              void* d_out, int out_size)
{
    const float* x     = (const float*)d_in[0];
    const float* Wq    = (const float*)d_in[1];
    const float* bq    = (const float*)d_in[2];
    const float* Wk    = (const float*)d_in[3];
    const float* bk    = (const float*)d_in[4];
    const float* Wv    = (const float*)d_in[5];
    const float* bv    = (const float*)d_in[6];
    const float* Wo    = (const float*)d_in[7];
    const float* bo    = (const float*)d_in[8];
    const float* gamma = (const float*)d_in[9];
    const float* beta  = (const float*)d_in[10];

    float* out  = (float*)d_out;
    float* attn = out + (size_t)kS * kD;

    cudaFuncSetAttribute(logits_kernel, cudaFuncAttributeMaxDynamicSharedMemorySize, LG_SMEM);
    cudaFuncSetAttribute(pv_kernel,     cudaFuncAttributeMaxDynamicSharedMemorySize, PV_SMEM);

    xsplit_kernel<<<kS * kD / 4 / 256, 256>>>(x);
    wsplit_kernel<<<dim3(kD * kD / 4 / 256, 3), 256>>>(Wq, Wk, Wv);
    qkv_kernel<<<dim3(48, 8, 3), 256>>>(bq, bk, bv);
    vsplit_kernel<<<dim3(192, 8), 256>>>();
    logits_kernel<<<dim3(24, 24, 8), 256, LG_SMEM>>>(attn);
    entmax_kernel<<<dim3(kS / 8, kH), 256>>>(attn);
    pv_kernel<<<dim3(48, 8), 256, PV_SMEM>>>(attn);
    out_kernel<<<kS / 16, 256>>>(x, Wo, bo, gamma, beta, out);
}

// round 14
// speedup vs baseline: 1.4652x; 1.1194x over previous
#include <cuda_runtime.h>
#include <cuda_bf16.h>
#include <cstdint>

#define kS 3072
#define kD 512
#define kH 8
#define NEWT 6

__device__ __nv_bfloat16 g_qc[(size_t)kH * kS * 192];
__device__ __nv_bfloat16 g_kc[(size_t)kH * kS * 192];
__device__ float g_v[(size_t)kH * kS * 64];
__device__ float g_ctx[(size_t)kS * kD];               // outmm result (pre-LN)
__device__ __nv_bfloat16 g_xh[(size_t)kS * kD];
__device__ __nv_bfloat16 g_xl[(size_t)kS * kD];
__device__ __nv_bfloat16 g_wth[(size_t)4 * kD * kD];   // [z][n][k], z=3 -> Wo
__device__ __nv_bfloat16 g_wtl[(size_t)4 * kD * kD];
__device__ __nv_bfloat16 g_vth[(size_t)kH * 64 * kS];  // [h][dv][j]
__device__ __nv_bfloat16 g_vtl[(size_t)kH * 64 * kS];
__device__ __nv_bfloat16 g_cth[(size_t)kS * kD];       // ctx hi/lo [m][k]
__device__ __nv_bfloat16 g_ctl[(size_t)kS * kD];

// ======================= helpers =======================
__device__ __forceinline__ uint32_t smem_u32(const void* p) {
    uint32_t a;
    asm("{ .reg .u64 t; cvta.to.shared.u64 t, %1; cvt.u32.u64 %0, t; }" : "=r"(a) : "l"(p));
    return a;
}
__device__ __forceinline__ void ldm_x4(uint32_t* r, uint32_t addr) {
    asm volatile("ldmatrix.sync.aligned.m8n8.x4.shared.b16 {%0,%1,%2,%3}, [%4];"
                 : "=r"(r[0]), "=r"(r[1]), "=r"(r[2]), "=r"(r[3]) : "r"(addr));
}
__device__ __forceinline__ void mma16816(float* c, const uint32_t* a, uint32_t b0, uint32_t b1) {
    asm volatile("mma.sync.aligned.m16n8k16.row.col.f32.bf16.bf16.f32 "
                 "{%0,%1,%2,%3}, {%4,%5,%6,%7}, {%8,%9}, {%0,%1,%2,%3};"
                 : "+f"(c[0]), "+f"(c[1]), "+f"(c[2]), "+f"(c[3])
                 : "r"(a[0]), "r"(a[1]), "r"(a[2]), "r"(a[3]), "r"(b0), "r"(b1));
}
#define CP_ASYNC16(saddr, gptr) \
    asm volatile("cp.async.cg.shared.global [%0], [%1], 16;" :: "r"(saddr), "l"(gptr))
#define CP_COMMIT() asm volatile("cp.async.commit_group;" ::: "memory")
#define CP_WAIT1()  asm volatile("cp.async.wait_group 1;" ::: "memory")
#define CP_WAIT0()  asm volatile("cp.async.wait_group 0;" ::: "memory")

__device__ __forceinline__ void split4(float4 f, uint32_t& h01, uint32_t& h23,
                                       uint32_t& l01, uint32_t& l23) {
    __nv_bfloat16 h0 = __float2bfloat16(f.x);
    __nv_bfloat16 h1 = __float2bfloat16(f.y);
    __nv_bfloat16 h2 = __float2bfloat16(f.z);
    __nv_bfloat16 h3 = __float2bfloat16(f.w);
    __nv_bfloat16 l0 = __float2bfloat16(f.x - __bfloat162float(h0));
    __nv_bfloat16 l1 = __float2bfloat16(f.y - __bfloat162float(h1));
    __nv_bfloat16 l2 = __float2bfloat16(f.z - __bfloat162float(h2));
    __nv_bfloat16 l3 = __float2bfloat16(f.w - __bfloat162float(h3));
    h01 = ((uint32_t)__bfloat16_as_ushort(h1) << 16) | __bfloat16_as_ushort(h0);
    h23 = ((uint32_t)__bfloat16_as_ushort(h3) << 16) | __bfloat16_as_ushort(h2);
    l01 = ((uint32_t)__bfloat16_as_ushort(l1) << 16) | __bfloat16_as_ushort(l0);
    l23 = ((uint32_t)__bfloat16_as_ushort(l3) << 16) | __bfloat16_as_ushort(l2);
}
__device__ __forceinline__ void split2(float a, float b, uint32_t& hh, uint32_t& ll) {
    __nv_bfloat16 h0 = __float2bfloat16(a);
    __nv_bfloat16 h1 = __float2bfloat16(b);
    __nv_bfloat16 l0 = __float2bfloat16(a - __bfloat162float(h0));
    __nv_bfloat16 l1 = __float2bfloat16(b - __bfloat162float(h1));
    hh = ((uint32_t)__bfloat16_as_ushort(h1) << 16) | __bfloat16_as_ushort(h0);
    ll = ((uint32_t)__bfloat16_as_ushort(l1) << 16) | __bfloat16_as_ushort(l0);
}

// ================= Prepass A: x -> hi/lo bf16 =================
__global__ __launch_bounds__(256) void xsplit_kernel(const float* __restrict__ x)
{
    int i = blockIdx.x * 256 + threadIdx.x;
    float4 v = ((const float4*)x)[i];
    uint32_t h01, h23, l01, l23;
    split4(v, h01, h23, l01, l23);
    ((uint2*)g_xh)[i] = make_uint2(h01, h23);
    ((uint2*)g_xl)[i] = make_uint2(l01, l23);
}

// ================= Prepass B: W -> transposed hi/lo bf16 (z=3 -> Wo) =================
__global__ __launch_bounds__(256) void wsplit_kernel(
    const float* __restrict__ Wq, const float* __restrict__ Wk,
    const float* __restrict__ Wv, const float* __restrict__ Wo)
{
    const int z = blockIdx.y;
    const float* W = (z == 0) ? Wq : (z == 1) ? Wk : (z == 2) ? Wv : Wo;
    int i = blockIdx.x * 256 + threadIdx.x;
    int n = i >> 7;
    int kq = (i & 127) * 4;
    float4 v;
    v.x = W[(size_t)(kq + 0) * kD + n];
    v.y = W[(size_t)(kq + 1) * kD + n];
    v.z = W[(size_t)(kq + 2) * kD + n];
    v.w = W[(size_t)(kq + 3) * kD + n];
    uint32_t h01, h23, l01, l23;
    split4(v, h01, h23, l01, l23);
    size_t o = ((size_t)z * kD + n) * kD + kq;
    *(uint2*)&g_wth[o] = make_uint2(h01, h23);
    *(uint2*)&g_wtl[o] = make_uint2(l01, l23);
}

// ================= Prepass C: V -> transposed hi/lo bf16 [h][dv][j] =================
__global__ __launch_bounds__(256) void vsplit_kernel()
{
    const int h = blockIdx.y;
    const int dv = blockIdx.x / 3;
    const int j = (blockIdx.x % 3) * 1024 + threadIdx.x * 4;
    float4 f;
    f.x = g_v[((size_t)h * kS + j + 0) * 64 + dv];
    f.y = g_v[((size_t)h * kS + j + 1) * 64 + dv];
    f.z = g_v[((size_t)h * kS + j + 2) * 64 + dv];
    f.w = g_v[((size_t)h * kS + j + 3) * 64 + dv];
    uint32_t h01, h23, l01, l23;
    split4(f, h01, h23, l01, l23);
    size_t o = ((size_t)h * 64 + dv) * kS + j;
    *(uint2*)&g_vth[o] = make_uint2(h01, h23);
    *(uint2*)&g_vtl[o] = make_uint2(l01, l23);
}

// ================= Kernel 1: QKV projections (HMMA) =================
#define QK_STR 72
__global__ __launch_bounds__(256) void qkv_kernel(
    const float* __restrict__ bq, const float* __restrict__ bk, const float* __restrict__ bv)
{
    __shared__ __align__(16) char s[4 * 64 * QK_STR * 2];
    char* sAh = s;
    char* sAl = s + 64 * QK_STR * 2;
    char* sBh = s + 2 * 64 * QK_STR * 2;
    char* sBl = s + 3 * 64 * QK_STR * 2;

    const int m0 = blockIdx.x * 64;
    const int h  = blockIdx.y;
    const int z  = blockIdx.z;
    const int n0 = h * 64;
    const float* bias = (z == 0) ? bq : (z == 1) ? bk : bv;
    const float scale = (z == 0) ? 0.125f : 1.0f;

    const int tid = threadIdx.x, wid = tid >> 5, lane = tid & 31;
    const uint32_t ahB = smem_u32(sAh), alB = smem_u32(sAl);
    const uint32_t bhB = smem_u32(sBh), blB = smem_u32(sBl);

    const int wm = (wid & 3) * 16;
    const int wn = (wid >> 2) * 32;
    const int arow = lane & 15, ak = (lane >> 4) * 8;

    float acc[4][4];
    #pragma unroll
    for (int j = 0; j < 4; j++)
        #pragma unroll
        for (int q = 0; q < 4; q++) acc[j][q] = 0.f;

    #pragma unroll 1
    for (int k0 = 0; k0 < kD; k0 += 64) {
        __syncthreads();
        #pragma unroll
        for (int t = 0; t < 4; t++) {
            int i = tid + t * 256;
            int r = i >> 4, c4 = (i & 15) * 4;
            uint32_t off = (uint32_t)r * (QK_STR * 2) + (uint32_t)c4 * 2;
            size_t ax = (size_t)(m0 + r) * kD + k0 + c4;
            *(uint2*)(sAh + off) = *(const uint2*)&g_xh[ax];
            *(uint2*)(sAl + off) = *(const uint2*)&g_xl[ax];
            size_t bx = ((size_t)z * kD + n0 + r) * kD + k0 + c4;
            *(uint2*)(sBh + off) = *(const uint2*)&g_wth[bx];
            *(uint2*)(sBl + off) = *(const uint2*)&g_wtl[bx];
        }
        __syncthreads();

        #pragma unroll
        for (int ks = 0; ks < 4; ks++) {
            uint32_t koff = (uint32_t)(ks * 16 + ak) * 2;
            uint32_t ah[4], al[4];
            ldm_x4(ah, ahB + (uint32_t)(wm + arow) * (QK_STR * 2) + koff);
            ldm_x4(al, alB + (uint32_t)(wm + arow) * (QK_STR * 2) + koff);
            uint32_t bh[2][4], bl[2][4];
            #pragma unroll
            for (int nb = 0; nb < 2; nb++) {
                ldm_x4(bh[nb], bhB + (uint32_t)(wn + nb * 16 + arow) * (QK_STR * 2) + koff);
                ldm_x4(bl[nb], blB + (uint32_t)(wn + nb * 16 + arow) * (QK_STR * 2) + koff);
            }
            #pragma unroll
            for (int nb = 0; nb < 2; nb++) {
                mma16816(acc[nb * 2 + 0], ah, bh[nb][0], bh[nb][2]);
                mma16816(acc[nb * 2 + 1], ah, bh[nb][1], bh[nb][3]);
                mma16816(acc[nb * 2 + 0], ah, bl[nb][0], bl[nb][2]);
                mma16816(acc[nb * 2 + 1], ah, bl[nb][1], bl[nb][3]);
                mma16816(acc[nb * 2 + 0], al, bh[nb][0], bh[nb][2]);
                mma16816(acc[nb * 2 + 1], al, bh[nb][1], bh[nb][3]);
            }
        }
    }

    const int gId = lane >> 2, tig = lane & 3;
    if (z == 2) {
        #pragma unroll
        for (int nf = 0; nf < 4; nf++) {
            int dkc = wn + nf * 8 + tig * 2;
            int m_lo = m0 + wm + gId;
            float b0v = bias[n0 + dkc], b1v = bias[n0 + dkc + 1];
            *(float2*)&g_v[((size_t)h * kS + m_lo) * 64 + dkc] =
                make_float2(acc[nf][0] + b0v, acc[nf][1] + b1v);
            *(float2*)&g_v[((size_t)h * kS + m_lo + 8) * 64 + dkc] =
                make_float2(acc[nf][2] + b0v, acc[nf][3] + b1v);
        }
    } else {
        __nv_bfloat16* dstc = (z == 0) ? g_qc : g_kc;
        const bool isq = (z == 0);
        #pragma unroll
        for (int nf = 0; nf < 4; nf++) {
            int dkc = wn + nf * 8 + tig * 2;
            float b0v = bias[n0 + dkc], b1v = bias[n0 + dkc + 1];
            #pragma unroll
            for (int half = 0; half < 2; half++) {
                int m = m0 + wm + gId + half * 8;
                float v0 = (acc[nf][half * 2 + 0] + b0v) * scale;
                float v1 = (acc[nf][half * 2 + 1] + b1v) * scale;
                uint32_t hh, ll;
                split2(v0, v1, hh, ll);
                size_t base = ((size_t)h * kS + m) * 192 + dkc;
                *(uint32_t*)&dstc[base] = hh;
                if (isq) { *(uint32_t*)&dstc[base + 64] = hh; *(uint32_t*)&dstc[base + 128] = ll; }
                else     { *(uint32_t*)&dstc[base + 64] = ll; *(uint32_t*)&dstc[base + 128] = hh; }
            }
        }
    }
}

// ================= Kernel 2: logits (HMMA, cp.async 2-stage pipeline) =================
#define LG_STR   208
#define LG_STAGE (2 * 128 * LG_STR)
#define LG_SMEM  (2 * LG_STAGE)

__global__ __launch_bounds__(256, 2) void logits_kernel(float* __restrict__ logits)
{
    extern __shared__ char sm[];
    const int tid = threadIdx.x, wid = tid >> 5, lane = tid & 31;
    const int h = blockIdx.z;
    const int row0 = blockIdx.y * 128;
    const int col0 = blockIdx.x * 128;
    const uint32_t smBase = smem_u32(sm);

    #pragma unroll
    for (int s = 0; s < 2; s++) {
        const int k0 = s * 96;
        const uint32_t stA = smBase + s * LG_STAGE;
        const uint32_t stB = stA + 128 * LG_STR;
        #pragma unroll
        for (int t = 0; t < 6; t++) {
            int i = tid + t * 256;
            int r = i / 12, cp = i % 12;
            CP_ASYNC16(stA + (uint32_t)r * LG_STR + (uint32_t)cp * 16,
                       &g_qc[((size_t)h * kS + row0 + r) * 192 + k0 + cp * 8]);
            CP_ASYNC16(stB + (uint32_t)r * LG_STR + (uint32_t)cp * 16,
                       &g_kc[((size_t)h * kS + col0 + r) * 192 + k0 + cp * 8]);
        }
        CP_COMMIT();
    }

    const int wm = (wid & 3) * 32;
    const int wn = (wid >> 2) * 64;
    const int arow = lane & 15, ak = (lane >> 4) * 8;

    float acc[2][8][4];
    #pragma unroll
    for (int i = 0; i < 2; i++)
        #pragma unroll
        for (int j = 0; j < 8; j++)
            #pragma unroll
            for (int q = 0; q < 4; q++) acc[i][j][q] = 0.f;

    #pragma unroll
    for (int s = 0; s < 2; s++) {
        if (s == 0) { CP_WAIT1(); } else { CP_WAIT0(); }
        __syncthreads();
        const uint32_t saBase = smBase + s * LG_STAGE;
        const uint32_t sbBase = saBase + 128 * LG_STR;
        #pragma unroll
        for (int ks = 0; ks < 6; ks++) {
            uint32_t koff = (uint32_t)(ks * 16 + ak) * 2;
            uint32_t a0[4], a1[4];
            ldm_x4(a0, saBase + (uint32_t)(wm + arow) * LG_STR + koff);
            ldm_x4(a1, saBase + (uint32_t)(wm + 16 + arow) * LG_STR + koff);
            uint32_t b[4][4];
            #pragma unroll
            for (int nb = 0; nb < 4; nb++)
                ldm_x4(b[nb], sbBase + (uint32_t)(wn + nb * 16 + arow) * LG_STR + koff);
            #pragma unroll
            for (int nb = 0; nb < 4; nb++) {
                mma16816(acc[0][nb * 2 + 0], a0, b[nb][0], b[nb][2]);
                mma16816(acc[0][nb * 2 + 1], a0, b[nb][1], b[nb][3]);
                mma16816(acc[1][nb * 2 + 0], a1, b[nb][0], b[nb][2]);
                mma16816(acc[1][nb * 2 + 1], a1, b[nb][1], b[nb][3]);
            }
        }
        if (s == 0) __syncthreads();
    }

    const int gId = lane >> 2, tig = lane & 3;
    #pragma unroll
    for (int mf = 0; mf < 2; mf++) {
        #pragma unroll
        for (int nf = 0; nf < 8; nf++) {
            int c = col0 + wn + nf * 8 + tig * 2;
            int r_lo = row0 + wm + mf * 16 + gId;
            *(float2*)&logits[((size_t)h * kS + r_lo) * kS + c] =
                make_float2(acc[mf][nf][0], acc[mf][nf][1]);
            *(float2*)&logits[((size_t)h * kS + r_lo + 8) * kS + c] =
                make_float2(acc[mf][nf][2], acc[mf][nf][3]);
        }
    }
}

// ================= Kernel 3: entmax1.5, register-resident rows =================
__global__ __launch_bounds__(256, 1) void entmax_kernel(float* __restrict__ attn)
{
    const int h = blockIdx.y;
    const int tid = threadIdx.x, wid = tid >> 5, lane = tid & 31;
    const int row = blockIdx.x * 8 + wid;
    float4* rp = (float4*)(attn + ((size_t)(h * kS + row)) * kS);

    float4 v[24];
    #pragma unroll
    for (int i = 0; i < 24; i++) v[i] = rp[lane + i * 32];

    float mx = -3.4e38f;
    #pragma unroll
    for (int i = 0; i < 24; i++)
        mx = fmaxf(mx, fmaxf(fmaxf(v[i].x, v[i].y), fmaxf(v[i].z, v[i].w)));
    #pragma unroll
    for (int o = 16; o; o >>= 1) mx = fmaxf(mx, __shfl_xor_sync(0xffffffffu, mx, o));

    float sum = 0.f;
    #pragma unroll
    for (int i = 0; i < 24; i++) {
        v[i].x = (v[i].x - mx) * 0.5f; v[i].y = (v[i].y - mx) * 0.5f;
        v[i].z = (v[i].z - mx) * 0.5f; v[i].w = (v[i].w - mx) * 0.5f;
        sum += (v[i].x + v[i].y) + (v[i].z + v[i].w);
    }
    #pragma unroll
    for (int o = 16; o; o >>= 1) sum += __shfl_xor_sync(0xffffffffu, sum, o);

    float tau = fminf(fmaxf(sum * (1.0f / kS), -1.0f), -1e-6f);
    #pragma unroll 1
    for (int it = 0; it < NEWT; it++) {
        float g = 0.f, gp = 0.f;
        #pragma unroll
        for (int i = 0; i < 24; i++) {
            float t0 = fmaxf(v[i].x - tau, 0.f); g = fmaf(t0, t0, g); gp += t0;
            float t1 = fmaxf(v[i].y - tau, 0.f); g = fmaf(t1, t1, g); gp += t1;
            float t2 = fmaxf(v[i].z - tau, 0.f); g = fmaf(t2, t2, g); gp += t2;
            float t3 = fmaxf(v[i].w - tau, 0.f); g = fmaf(t3, t3, g); gp += t3;
        }
        #pragma unroll
        for (int o = 16; o; o >>= 1) {
            g  += __shfl_xor_sync(0xffffffffu, g, o);
            gp += __shfl_xor_sync(0xffffffffu, gp, o);
        }
        tau = tau + (g - 1.0f) / fmaxf(2.f * gp, 1e-20f);
        tau = fminf(fmaxf(tau, -1.0f), 0.0f);
    }

    #pragma unroll
    for (int i = 0; i < 24; i++) {
        float t;
        t = fmaxf(v[i].x - tau, 0.f); v[i].x = t * t;
        t = fmaxf(v[i].y - tau, 0.f); v[i].y = t * t;
        t = fmaxf(v[i].z - tau, 0.f); v[i].z = t * t;
        t = fmaxf(v[i].w - tau, 0.f); v[i].w = t * t;
        rp[lane + i * 32] = v[i];
    }
}

// ================= Kernel 4: ctx = P @ V (HMMA, double-buffered, prepacked V) =================
#define PV_STR   72
#define PV_STAGE (4 * 64 * PV_STR * 2)
#define PV_SMEM  (2 * PV_STAGE)

__global__ __launch_bounds__(256, 2) void pv_kernel(const float* __restrict__ p)
{
    extern __shared__ char sm[];

    const int tid = threadIdx.x, wid = tid >> 5, lane = tid & 31;
    const int h = blockIdx.y;
    const int row0 = blockIdx.x * 64;

    float acc[4][4];
    #pragma unroll
    for (int j = 0; j < 4; j++)
        #pragma unroll
        for (int q = 0; q < 4; q++) acc[j][q] = 0.f;

    const int arow = lane & 15, ak = (lane >> 4) * 8;
    const int wm = (wid & 3) * 16;
    const int wn = (wid >> 2) * 32;

    const int pr0 = tid >> 4;
    const int pc4 = (tid & 15) * 4;
    const int vdv = tid >> 4;
    const int vj  = (tid & 15) * 4;

    float4 pf_p[4];
    uint2  pf_vh[4], pf_vl[4];

    {
        char* smAh = sm;
        char* smAl = sm + 64 * PV_STR * 2;
        char* smBh = sm + 2 * 64 * PV_STR * 2;
        char* smBl = sm + 3 * 64 * PV_STR * 2;
        #pragma unroll
        for (int t = 0; t < 4; t++) {
            pf_p[t]  = *(const float4*)&p[((size_t)h * kS + row0 + pr0 + t * 16) * kS + pc4];
            pf_vh[t] = *(const uint2*)&g_vth[((size_t)h * 64 + vdv + t * 16) * kS + vj];
            pf_vl[t] = *(const uint2*)&g_vtl[((size_t)h * 64 + vdv + t * 16) * kS + vj];
        }
        #pragma unroll
        for (int t = 0; t < 4; t++) {
            uint32_t h01, h23, l01, l23;
            split4(pf_p[t], h01, h23, l01, l23);
            uint32_t offA = (uint32_t)(pr0 + t * 16) * (PV_STR * 2) + (uint32_t)pc4 * 2;
            *(uint2*)(smAh + offA) = make_uint2(h01, h23);
            *(uint2*)(smAl + offA) = make_uint2(l01, l23);
            uint32_t offB = (uint32_t)(vdv + t * 16) * (PV_STR * 2) + (uint32_t)vj * 2;
            *(uint2*)(smBh + offB) = pf_vh[t];
            *(uint2*)(smBl + offB) = pf_vl[t];
        }
    }
    __syncthreads();

    #pragma unroll 1
    for (int c = 0; c < 48; c++) {
        char* rd = sm + (c & 1) * PV_STAGE;
        char* wr = sm + ((c + 1) & 1) * PV_STAGE;
        const uint32_t ahB = smem_u32(rd);
        const uint32_t alB = ahB + 64 * PV_STR * 2;
        const uint32_t bhB = ahB + 2 * 64 * PV_STR * 2;
        const uint32_t blB = ahB + 3 * 64 * PV_STR * 2;

        if (c < 47) {
            const int j0 = (c + 1) * 64;
            #pragma unroll
            for (int t = 0; t < 4; t++) {
                pf_p[t]  = *(const float4*)&p[((size_t)h * kS + row0 + pr0 + t * 16) * kS + j0 + pc4];
                pf_vh[t] = *(const uint2*)&g_vth[((size_t)h * 64 + vdv + t * 16) * kS + j0 + vj];
                pf_vl[t] = *(const uint2*)&g_vtl[((size_t)h * 64 + vdv + t * 16) * kS + j0 + vj];
            }
        }

        #pragma unroll
        for (int ks = 0; ks < 4; ks++) {
            uint32_t koff = (uint32_t)(ks * 16 + ak) * 2;
            uint32_t ah[4], al[4];
            ldm_x4(ah, ahB + (uint32_t)(wm + arow) * (PV_STR * 2) + koff);
            ldm_x4(al, alB + (uint32_t)(wm + arow) * (PV_STR * 2) + koff);
            uint32_t bh[2][4], bl[2][4];
            #pragma unroll
            for (int nb = 0; nb < 2; nb++) {
                ldm_x4(bh[nb], bhB + (uint32_t)(wn + nb * 16 + arow) * (PV_STR * 2) + koff);
                ldm_x4(bl[nb], blB + (uint32_t)(wn + nb * 16 + arow) * (PV_STR * 2) + koff);
            }
            #pragma unroll
            for (int nb = 0; nb < 2; nb++) {
                mma16816(acc[nb * 2 + 0], ah, bh[nb][0], bh[nb][2]);
                mma16816(acc[nb * 2 + 1], ah, bh[nb][1], bh[nb][3]);
                mma16816(acc[nb * 2 + 0], ah, bl[nb][0], bl[nb][2]);
                mma16816(acc[nb * 2 + 1], ah, bl[nb][1], bl[nb][3]);
                mma16816(acc[nb * 2 + 0], al, bh[nb][0], bh[nb][2]);
                mma16816(acc[nb * 2 + 1], al, bh[nb][1], bh[nb][3]);
            }
        }

        if (c < 47) {
            char* smAh = wr;
            char* smAl = wr + 64 * PV_STR * 2;
            char* smBh = wr + 2 * 64 * PV_STR * 2;
            char* smBl = wr + 3 * 64 * PV_STR * 2;
            #pragma unroll
            for (int t = 0; t < 4; t++) {
                uint32_t h01, h23, l01, l23;
                split4(pf_p[t], h01, h23, l01, l23);
                uint32_t offA = (uint32_t)(pr0 + t * 16) * (PV_STR * 2) + (uint32_t)pc4 * 2;
                *(uint2*)(smAh + offA) = make_uint2(h01, h23);
                *(uint2*)(smAl + offA) = make_uint2(l01, l23);
                uint32_t offB = (uint32_t)(vdv + t * 16) * (PV_STR * 2) + (uint32_t)vj * 2;
                *(uint2*)(smBh + offB) = pf_vh[t];
                *(uint2*)(smBl + offB) = pf_vl[t];
            }
        }
        __syncthreads();
    }

    // epilogue: write ctx as hi/lo bf16 for the outmm GEMM
    const int gId = lane >> 2, tig = lane & 3;
    #pragma unroll
    for (int f = 0; f < 4; f++) {
        int cc = wn + (f >> 1) * 16 + (f & 1) * 8 + tig * 2;
        int r_lo = row0 + wm + gId;
        size_t o0 = (size_t)r_lo * kD + h * 64 + cc;
        size_t o1 = (size_t)(r_lo + 8) * kD + h * 64 + cc;
        uint32_t hh, ll;
        split2(acc[f][0], acc[f][1], hh, ll);
        *(uint32_t*)&g_cth[o0] = hh;
        *(uint32_t*)&g_ctl[o0] = ll;
        split2(acc[f][2], acc[f][3], hh, ll);
        *(uint32_t*)&g_cth[o1] = hh;
        *(uint32_t*)&g_ctl[o1] = ll;
    }
}

// ================= Kernel 5: out = ctx @ Wo + bo (HMMA) =================
__global__ __launch_bounds__(256) void outmm_kernel(const float* __restrict__ bo)
{
    __shared__ __align__(16) char s[4 * 64 * QK_STR * 2];
    char* sAh = s;
    char* sAl = s + 64 * QK_STR * 2;
    char* sBh = s + 2 * 64 * QK_STR * 2;
    char* sBl = s + 3 * 64 * QK_STR * 2;

    const int m0 = blockIdx.x * 64;
    const int n0 = blockIdx.y * 64;

    const int tid = threadIdx.x, wid = tid >> 5, lane = tid & 31;
    const uint32_t ahB = smem_u32(sAh), alB = smem_u32(sAl);
    const uint32_t bhB = smem_u32(sBh), blB = smem_u32(sBl);

    const int wm = (wid & 3) * 16;
    const int wn = (wid >> 2) * 32;
    const int arow = lane & 15, ak = (lane >> 4) * 8;

    float acc[4][4];
    #pragma unroll
    for (int j = 0; j < 4; j++)
        #pragma unroll
        for (int q = 0; q < 4; q++) acc[j][q] = 0.f;

    #pragma unroll 1
    for (int k0 = 0; k0 < kD; k0 += 64) {
        __syncthreads();
        #pragma unroll
        for (int t = 0; t < 4; t++) {
            int i = tid + t * 256;
            int r = i >> 4, c4 = (i & 15) * 4;
            uint32_t off = (uint32_t)r * (QK_STR * 2) + (uint32_t)c4 * 2;
            size_t ax = (size_t)(m0 + r) * kD + k0 + c4;
            *(uint2*)(sAh + off) = *(const uint2*)&g_cth[ax];
            *(uint2*)(sAl + off) = *(const uint2*)&g_ctl[ax];
            size_t bx = ((size_t)3 * kD + n0 + r) * kD + k0 + c4;
            *(uint2*)(sBh + off) = *(const uint2*)&g_wth[bx];
            *(uint2*)(sBl + off) = *(const uint2*)&g_wtl[bx];
        }
        __syncthreads();

        #pragma unroll
        for (int ks = 0; ks < 4; ks++) {
            uint32_t koff = (uint32_t)(ks * 16 + ak) * 2;
            uint32_t ah[4], al[4];
            ldm_x4(ah, ahB + (uint32_t)(wm + arow) * (QK_STR * 2) + koff);
            ldm_x4(al, alB + (uint32_t)(wm + arow) * (QK_STR * 2) + koff);
            uint32_t bh[2][4], bl[2][4];
            #pragma unroll
            for (int nb = 0; nb < 2; nb++) {
                ldm_x4(bh[nb], bhB + (uint32_t)(wn + nb * 16 + arow) * (QK_STR * 2) + koff);
                ldm_x4(bl[nb], blB + (uint32_t)(wn + nb * 16 + arow) * (QK_STR * 2) + koff);
            }
            #pragma unroll
            for (int nb = 0; nb < 2; nb++) {
                mma16816(acc[nb * 2 + 0], ah, bh[nb][0], bh[nb][2]);
                mma16816(acc[nb * 2 + 1], ah, bh[nb][1], bh[nb][3]);
                mma16816(acc[nb * 2 + 0], ah, bl[nb][0], bl[nb][2]);
                mma16816(acc[nb * 2 + 1], ah, bl[nb][1], bl[nb][3]);
                mma16816(acc[nb * 2 + 0], al, bh[nb][0], bh[nb][2]);
                mma16816(acc[nb * 2 + 1], al, bh[nb][1], bh[nb][3]);
            }
        }
    }

    const int gId = lane >> 2, tig = lane & 3;
    #pragma unroll
    for (int nf = 0; nf < 4; nf++) {
        int dkc = wn + nf * 8 + tig * 2;
        int m_lo = m0 + wm + gId;
        float b0v = bo[n0 + dkc], b1v = bo[n0 + dkc + 1];
        *(float2*)&g_ctx[(size_t)m_lo * kD + n0 + dkc] =
            make_float2(acc[nf][0] + b0v, acc[nf][1] + b1v);
        *(float2*)&g_ctx[(size_t)(m_lo + 8) * kD + n0 + dkc] =
            make_float2(acc[nf][2] + b0v, acc[nf][3] + b1v);
    }
}

// ================= Kernel 6: residual + LayerNorm =================
__global__ __launch_bounds__(256) void ln_kernel(
    const float* __restrict__ x,
    const float* __restrict__ gamma, const float* __restrict__ beta,
    float* __restrict__ out)
{
    __shared__ float sC[16 * kD];

    const int m0  = blockIdx.x * 16;
    const int tid = threadIdx.x;

    for (int i = tid; i < 2048; i += 256) {
        float4 c = ((const float4*)&g_ctx[(size_t)m0 * kD])[i];
        float4 r = ((const float4*)&x[(size_t)m0 * kD])[i];
        c.x += r.x; c.y += r.y; c.z += r.z; c.w += r.w;
        ((float4*)sC)[i] = c;
    }
    __syncthreads();

    const int wid = tid >> 5, lane = tid & 31;
    #pragma unroll 1
    for (int rr = 0; rr < 2; rr++) {
        int r = wid * 2 + rr;
        float s = 0.f, ss = 0.f;
        for (int i = lane; i < kD; i += 32) {
            float v = sC[r * kD + i];
            s += v; ss = fmaf(v, v, ss);
        }
        #pragma unroll
        for (int o = 16; o; o >>= 1) {
            s  += __shfl_xor_sync(0xffffffffu, s, o);
            ss += __shfl_xor_sync(0xffffffffu, ss, o);
        }
        float mu  = s * (1.f / kD);
        float var = ss * (1.f / kD) - mu * mu;
        float inv = rsqrtf(var + 1e-6f);
        for (int i = lane; i < kD; i += 32) {
            float v = sC[r * kD + i];
            out[(size_t)(m0 + r) * kD + i] = (v - mu) * inv * gamma[i] + beta[i];
        }
    }
}

// ================= launcher =================
extern "C" void kernel_launch(void* const* d_in, const int* in_sizes, int n_in,
                              void* d_out, int out_size)
{
    const float* x     = (const float*)d_in[0];
    const float* Wq    = (const float*)d_in[1];
    const float* bq    = (const float*)d_in[2];
    const float* Wk    = (const float*)d_in[3];
    const float* bk    = (const float*)d_in[4];
    const float* Wv    = (const float*)d_in[5];
    const float* bv    = (const float*)d_in[6];
    const float* Wo    = (const float*)d_in[7];
    const float* bo    = (const float*)d_in[8];
    const float* gamma = (const float*)d_in[9];
    const float* beta  = (const float*)d_in[10];

    float* out  = (float*)d_out;
    float* attn = out + (size_t)kS * kD;

    cudaFuncSetAttribute(logits_kernel, cudaFuncAttributeMaxDynamicSharedMemorySize, LG_SMEM);
    cudaFuncSetAttribute(pv_kernel,     cudaFuncAttributeMaxDynamicSharedMemorySize, PV_SMEM);

    xsplit_kernel<<<kS * kD / 4 / 256, 256>>>(x);
    wsplit_kernel<<<dim3(kD * kD / 4 / 256, 4), 256>>>(Wq, Wk, Wv, Wo);
    qkv_kernel<<<dim3(48, 8, 3), 256>>>(bq, bk, bv);
    vsplit_kernel<<<dim3(192, 8), 256>>>();
    logits_kernel<<<dim3(24, 24, 8), 256, LG_SMEM>>>(attn);
    entmax_kernel<<<dim3(kS / 8, kH), 256>>>(attn);
    pv_kernel<<<dim3(48, 8), 256, PV_SMEM>>>(attn);
    outmm_kernel<<<dim3(48, 8), 256>>>(bo);
    ln_kernel<<<kS / 16, 256>>>(x, gamma, beta, out);
}

// round 16
// speedup vs baseline: 1.4833x; 1.0124x over previous
#include <cuda_runtime.h>
#include <cuda_bf16.h>
#include <cstdint>

#define kS 3072
#define kD 512
#define kH 8
#define NEWT 6

__device__ __nv_bfloat16 g_qc[(size_t)kH * kS * 192];
__device__ __nv_bfloat16 g_kc[(size_t)kH * kS * 192];
__device__ float g_v[(size_t)kH * kS * 64];
__device__ float g_ctx[(size_t)kS * kD];               // outmm result (pre-LN)
__device__ __nv_bfloat16 g_xh[(size_t)kS * kD];
__device__ __nv_bfloat16 g_xl[(size_t)kS * kD];
__device__ __nv_bfloat16 g_wth[(size_t)4 * kD * kD];   // [z][n][k], z=3 -> Wo
__device__ __nv_bfloat16 g_wtl[(size_t)4 * kD * kD];
__device__ __nv_bfloat16 g_vth[(size_t)kH * 64 * kS];  // [h][dv][j]
__device__ __nv_bfloat16 g_vtl[(size_t)kH * 64 * kS];
__device__ __nv_bfloat16 g_cth[(size_t)kS * kD];       // ctx hi/lo [m][k]
__device__ __nv_bfloat16 g_ctl[(size_t)kS * kD];
__device__ float g_pvp[2][(size_t)kS * kD];            // pv K-split partials

// ======================= helpers =======================
__device__ __forceinline__ uint32_t smem_u32(const void* p) {
    uint32_t a;
    asm("{ .reg .u64 t; cvta.to.shared.u64 t, %1; cvt.u32.u64 %0, t; }" : "=r"(a) : "l"(p));
    return a;
}
__device__ __forceinline__ void ldm_x4(uint32_t* r, uint32_t addr) {
    asm volatile("ldmatrix.sync.aligned.m8n8.x4.shared.b16 {%0,%1,%2,%3}, [%4];"
                 : "=r"(r[0]), "=r"(r[1]), "=r"(r[2]), "=r"(r[3]) : "r"(addr));
}
__device__ __forceinline__ void mma16816(float* c, const uint32_t* a, uint32_t b0, uint32_t b1) {
    asm volatile("mma.sync.aligned.m16n8k16.row.col.f32.bf16.bf16.f32 "
                 "{%0,%1,%2,%3}, {%4,%5,%6,%7}, {%8,%9}, {%0,%1,%2,%3};"
                 : "+f"(c[0]), "+f"(c[1]), "+f"(c[2]), "+f"(c[3])
                 : "r"(a[0]), "r"(a[1]), "r"(a[2]), "r"(a[3]), "r"(b0), "r"(b1));
}
#define CP_ASYNC16(saddr, gptr) \
    asm volatile("cp.async.cg.shared.global [%0], [%1], 16;" :: "r"(saddr), "l"(gptr))
#define CP_COMMIT() asm volatile("cp.async.commit_group;" ::: "memory")
#define CP_WAIT1()  asm volatile("cp.async.wait_group 1;" ::: "memory")
#define CP_WAIT0()  asm volatile("cp.async.wait_group 0;" ::: "memory")

__device__ __forceinline__ void split4(float4 f, uint32_t& h01, uint32_t& h23,
                                       uint32_t& l01, uint32_t& l23) {
    __nv_bfloat16 h0 = __float2bfloat16(f.x);
    __nv_bfloat16 h1 = __float2bfloat16(f.y);
    __nv_bfloat16 h2 = __float2bfloat16(f.z);
    __nv_bfloat16 h3 = __float2bfloat16(f.w);
    __nv_bfloat16 l0 = __float2bfloat16(f.x - __bfloat162float(h0));
    __nv_bfloat16 l1 = __float2bfloat16(f.y - __bfloat162float(h1));
    __nv_bfloat16 l2 = __float2bfloat16(f.z - __bfloat162float(h2));
    __nv_bfloat16 l3 = __float2bfloat16(f.w - __bfloat162float(h3));
    h01 = ((uint32_t)__bfloat16_as_ushort(h1) << 16) | __bfloat16_as_ushort(h0);
    h23 = ((uint32_t)__bfloat16_as_ushort(h3) << 16) | __bfloat16_as_ushort(h2);
    l01 = ((uint32_t)__bfloat16_as_ushort(l1) << 16) | __bfloat16_as_ushort(l0);
    l23 = ((uint32_t)__bfloat16_as_ushort(l3) << 16) | __bfloat16_as_ushort(l2);
}
__device__ __forceinline__ void split2(float a, float b, uint32_t& hh, uint32_t& ll) {
    __nv_bfloat16 h0 = __float2bfloat16(a);
    __nv_bfloat16 h1 = __float2bfloat16(b);
    __nv_bfloat16 l0 = __float2bfloat16(a - __bfloat162float(h0));
    __nv_bfloat16 l1 = __float2bfloat16(b - __bfloat162float(h1));
    hh = ((uint32_t)__bfloat16_as_ushort(h1) << 16) | __bfloat16_as_ushort(h0);
    ll = ((uint32_t)__bfloat16_as_ushort(l1) << 16) | __bfloat16_as_ushort(l0);
}

// ================= Prepass A: x -> hi/lo bf16 =================
__global__ __launch_bounds__(256) void xsplit_kernel(const float* __restrict__ x)
{
    int i = blockIdx.x * 256 + threadIdx.x;
    float4 v = ((const float4*)x)[i];
    uint32_t h01, h23, l01, l23;
    split4(v, h01, h23, l01, l23);
    ((uint2*)g_xh)[i] = make_uint2(h01, h23);
    ((uint2*)g_xl)[i] = make_uint2(l01, l23);
}

// ================= Prepass B: W -> transposed hi/lo bf16 (z=3 -> Wo) =================
__global__ __launch_bounds__(256) void wsplit_kernel(
    const float* __restrict__ Wq, const float* __restrict__ Wk,
    const float* __restrict__ Wv, const float* __restrict__ Wo)
{
    const int z = blockIdx.y;
    const float* W = (z == 0) ? Wq : (z == 1) ? Wk : (z == 2) ? Wv : Wo;
    int i = blockIdx.x * 256 + threadIdx.x;
    int n = i >> 7;
    int kq = (i & 127) * 4;
    float4 v;
    v.x = W[(size_t)(kq + 0) * kD + n];
    v.y = W[(size_t)(kq + 1) * kD + n];
    v.z = W[(size_t)(kq + 2) * kD + n];
    v.w = W[(size_t)(kq + 3) * kD + n];
    uint32_t h01, h23, l01, l23;
    split4(v, h01, h23, l01, l23);
    size_t o = ((size_t)z * kD + n) * kD + kq;
    *(uint2*)&g_wth[o] = make_uint2(h01, h23);
    *(uint2*)&g_wtl[o] = make_uint2(l01, l23);
}

// ================= Prepass C: V -> transposed hi/lo bf16 [h][dv][j] =================
__global__ __launch_bounds__(256) void vsplit_kernel()
{
    const int h = blockIdx.y;
    const int dv = blockIdx.x / 3;
    const int j = (blockIdx.x % 3) * 1024 + threadIdx.x * 4;
    float4 f;
    f.x = g_v[((size_t)h * kS + j + 0) * 64 + dv];
    f.y = g_v[((size_t)h * kS + j + 1) * 64 + dv];
    f.z = g_v[((size_t)h * kS + j + 2) * 64 + dv];
    f.w = g_v[((size_t)h * kS + j + 3) * 64 + dv];
    uint32_t h01, h23, l01, l23;
    split4(f, h01, h23, l01, l23);
    size_t o = ((size_t)h * 64 + dv) * kS + j;
    *(uint2*)&g_vth[o] = make_uint2(h01, h23);
    *(uint2*)&g_vtl[o] = make_uint2(l01, l23);
}

// ================= Kernel 1: QKV projections (HMMA) =================
#define QK_STR 72
__global__ __launch_bounds__(256) void qkv_kernel(
    const float* __restrict__ bq, const float* __restrict__ bk, const float* __restrict__ bv)
{
    __shared__ __align__(16) char s[4 * 64 * QK_STR * 2];
    char* sAh = s;
    char* sAl = s + 64 * QK_STR * 2;
    char* sBh = s + 2 * 64 * QK_STR * 2;
    char* sBl = s + 3 * 64 * QK_STR * 2;

    const int m0 = blockIdx.x * 64;
    const int h  = blockIdx.y;
    const int z  = blockIdx.z;
    const int n0 = h * 64;
    const float* bias = (z == 0) ? bq : (z == 1) ? bk : bv;
    const float scale = (z == 0) ? 0.125f : 1.0f;

    const int tid = threadIdx.x, wid = tid >> 5, lane = tid & 31;
    const uint32_t ahB = smem_u32(sAh), alB = smem_u32(sAl);
    const uint32_t bhB = smem_u32(sBh), blB = smem_u32(sBl);

    const int wm = (wid & 3) * 16;
    const int wn = (wid >> 2) * 32;
    const int arow = lane & 15, ak = (lane >> 4) * 8;

    float acc[4][4];
    #pragma unroll
    for (int j = 0; j < 4; j++)
        #pragma unroll
        for (int q = 0; q < 4; q++) acc[j][q] = 0.f;

    #pragma unroll 1
    for (int k0 = 0; k0 < kD; k0 += 64) {
        __syncthreads();
        #pragma unroll
        for (int t = 0; t < 4; t++) {
            int i = tid + t * 256;
            int r = i >> 4, c4 = (i & 15) * 4;
            uint32_t off = (uint32_t)r * (QK_STR * 2) + (uint32_t)c4 * 2;
            size_t ax = (size_t)(m0 + r) * kD + k0 + c4;
            *(uint2*)(sAh + off) = *(const uint2*)&g_xh[ax];
            *(uint2*)(sAl + off) = *(const uint2*)&g_xl[ax];
            size_t bx = ((size_t)z * kD + n0 + r) * kD + k0 + c4;
            *(uint2*)(sBh + off) = *(const uint2*)&g_wth[bx];
            *(uint2*)(sBl + off) = *(const uint2*)&g_wtl[bx];
        }
        __syncthreads();

        #pragma unroll
        for (int ks = 0; ks < 4; ks++) {
            uint32_t koff = (uint32_t)(ks * 16 + ak) * 2;
            uint32_t ah[4], al[4];
            ldm_x4(ah, ahB + (uint32_t)(wm + arow) * (QK_STR * 2) + koff);
            ldm_x4(al, alB + (uint32_t)(wm + arow) * (QK_STR * 2) + koff);
            uint32_t bh[2][4], bl[2][4];
            #pragma unroll
            for (int nb = 0; nb < 2; nb++) {
                ldm_x4(bh[nb], bhB + (uint32_t)(wn + nb * 16 + arow) * (QK_STR * 2) + koff);
                ldm_x4(bl[nb], blB + (uint32_t)(wn + nb * 16 + arow) * (QK_STR * 2) + koff);
            }
            #pragma unroll
            for (int nb = 0; nb < 2; nb++) {
                mma16816(acc[nb * 2 + 0], ah, bh[nb][0], bh[nb][2]);
                mma16816(acc[nb * 2 + 1], ah, bh[nb][1], bh[nb][3]);
                mma16816(acc[nb * 2 + 0], ah, bl[nb][0], bl[nb][2]);
                mma16816(acc[nb * 2 + 1], ah, bl[nb][1], bl[nb][3]);
                mma16816(acc[nb * 2 + 0], al, bh[nb][0], bh[nb][2]);
                mma16816(acc[nb * 2 + 1], al, bh[nb][1], bh[nb][3]);
            }
        }
    }

    const int gId = lane >> 2, tig = lane & 3;
    if (z == 2) {
        #pragma unroll
        for (int nf = 0; nf < 4; nf++) {
            int dkc = wn + nf * 8 + tig * 2;
            int m_lo = m0 + wm + gId;
            float b0v = bias[n0 + dkc], b1v = bias[n0 + dkc + 1];
            *(float2*)&g_v[((size_t)h * kS + m_lo) * 64 + dkc] =
                make_float2(acc[nf][0] + b0v, acc[nf][1] + b1v);
            *(float2*)&g_v[((size_t)h * kS + m_lo + 8) * 64 + dkc] =
                make_float2(acc[nf][2] + b0v, acc[nf][3] + b1v);
        }
    } else {
        __nv_bfloat16* dstc = (z == 0) ? g_qc : g_kc;
        const bool isq = (z == 0);
        #pragma unroll
        for (int nf = 0; nf < 4; nf++) {
            int dkc = wn + nf * 8 + tig * 2;
            float b0v = bias[n0 + dkc], b1v = bias[n0 + dkc + 1];
            #pragma unroll
            for (int half = 0; half < 2; half++) {
                int m = m0 + wm + gId + half * 8;
                float v0 = (acc[nf][half * 2 + 0] + b0v) * scale;
                float v1 = (acc[nf][half * 2 + 1] + b1v) * scale;
                uint32_t hh, ll;
                split2(v0, v1, hh, ll);
                size_t base = ((size_t)h * kS + m) * 192 + dkc;
                *(uint32_t*)&dstc[base] = hh;
                if (isq) { *(uint32_t*)&dstc[base + 64] = hh; *(uint32_t*)&dstc[base + 128] = ll; }
                else     { *(uint32_t*)&dstc[base + 64] = ll; *(uint32_t*)&dstc[base + 128] = hh; }
            }
        }
    }
}

// ================= Kernel 2: logits (HMMA, cp.async 2-stage pipeline) =================
#define LG_STR   208
#define LG_STAGE (2 * 128 * LG_STR)
#define LG_SMEM  (2 * LG_STAGE)

__global__ __launch_bounds__(256, 2) void logits_kernel(float* __restrict__ logits)
{
    extern __shared__ char sm[];
    const int tid = threadIdx.x, wid = tid >> 5, lane = tid & 31;
    const int h = blockIdx.z;
    const int row0 = blockIdx.y * 128;
    const int col0 = blockIdx.x * 128;
    const uint32_t smBase = smem_u32(sm);

    #pragma unroll
    for (int s = 0; s < 2; s++) {
        const int k0 = s * 96;
        const uint32_t stA = smBase + s * LG_STAGE;
        const uint32_t stB = stA + 128 * LG_STR;
        #pragma unroll
        for (int t = 0; t < 6; t++) {
            int i = tid + t * 256;
            int r = i / 12, cp = i % 12;
            CP_ASYNC16(stA + (uint32_t)r * LG_STR + (uint32_t)cp * 16,
                       &g_qc[((size_t)h * kS + row0 + r) * 192 + k0 + cp * 8]);
            CP_ASYNC16(stB + (uint32_t)r * LG_STR + (uint32_t)cp * 16,
                       &g_kc[((size_t)h * kS + col0 + r) * 192 + k0 + cp * 8]);
        }
        CP_COMMIT();
    }

    const int wm = (wid & 3) * 32;
    const int wn = (wid >> 2) * 64;
    const int arow = lane & 15, ak = (lane >> 4) * 8;

    float acc[2][8][4];
    #pragma unroll
    for (int i = 0; i < 2; i++)
        #pragma unroll
        for (int j = 0; j < 8; j++)
            #pragma unroll
            for (int q = 0; q < 4; q++) acc[i][j][q] = 0.f;

    #pragma unroll
    for (int s = 0; s < 2; s++) {
        if (s == 0) { CP_WAIT1(); } else { CP_WAIT0(); }
        __syncthreads();
        const uint32_t saBase = smBase + s * LG_STAGE;
        const uint32_t sbBase = saBase + 128 * LG_STR;
        #pragma unroll
        for (int ks = 0; ks < 6; ks++) {
            uint32_t koff = (uint32_t)(ks * 16 + ak) * 2;
            uint32_t a0[4], a1[4];
            ldm_x4(a0, saBase + (uint32_t)(wm + arow) * LG_STR + koff);
            ldm_x4(a1, saBase + (uint32_t)(wm + 16 + arow) * LG_STR + koff);
            uint32_t b[4][4];
            #pragma unroll
            for (int nb = 0; nb < 4; nb++)
                ldm_x4(b[nb], sbBase + (uint32_t)(wn + nb * 16 + arow) * LG_STR + koff);
            #pragma unroll
            for (int nb = 0; nb < 4; nb++) {
                mma16816(acc[0][nb * 2 + 0], a0, b[nb][0], b[nb][2]);
                mma16816(acc[0][nb * 2 + 1], a0, b[nb][1], b[nb][3]);
                mma16816(acc[1][nb * 2 + 0], a1, b[nb][0], b[nb][2]);
                mma16816(acc[1][nb * 2 + 1], a1, b[nb][1], b[nb][3]);
            }
        }
        if (s == 0) __syncthreads();
    }

    const int gId = lane >> 2, tig = lane & 3;
    #pragma unroll
    for (int mf = 0; mf < 2; mf++) {
        #pragma unroll
        for (int nf = 0; nf < 8; nf++) {
            int c = col0 + wn + nf * 8 + tig * 2;
            int r_lo = row0 + wm + mf * 16 + gId;
            *(float2*)&logits[((size_t)h * kS + r_lo) * kS + c] =
                make_float2(acc[mf][nf][0], acc[mf][nf][1]);
            *(float2*)&logits[((size_t)h * kS + r_lo + 8) * kS + c] =
                make_float2(acc[mf][nf][2], acc[mf][nf][3]);
        }
    }
}

// ================= Kernel 3: entmax1.5, register-resident rows =================
__global__ __launch_bounds__(256, 2) void entmax_kernel(float* __restrict__ attn)
{
    const int h = blockIdx.y;
    const int tid = threadIdx.x, wid = tid >> 5, lane = tid & 31;
    const int row = blockIdx.x * 8 + wid;
    float4* rp = (float4*)(attn + ((size_t)(h * kS + row)) * kS);

    float4 v[24];
    #pragma unroll
    for (int i = 0; i < 24; i++) v[i] = rp[lane + i * 32];

    float mx = -3.4e38f;
    #pragma unroll
    for (int i = 0; i < 24; i++)
        mx = fmaxf(mx, fmaxf(fmaxf(v[i].x, v[i].y), fmaxf(v[i].z, v[i].w)));
    #pragma unroll
    for (int o = 16; o; o >>= 1) mx = fmaxf(mx, __shfl_xor_sync(0xffffffffu, mx, o));

    float sum = 0.f;
    #pragma unroll
    for (int i = 0; i < 24; i++) {
        v[i].x = (v[i].x - mx) * 0.5f; v[i].y = (v[i].y - mx) * 0.5f;
        v[i].z = (v[i].z - mx) * 0.5f; v[i].w = (v[i].w - mx) * 0.5f;
        sum += (v[i].x + v[i].y) + (v[i].z + v[i].w);
    }
    #pragma unroll
    for (int o = 16; o; o >>= 1) sum += __shfl_xor_sync(0xffffffffu, sum, o);

    float tau = fminf(fmaxf(sum * (1.0f / kS), -1.0f), -1e-6f);
    #pragma unroll 1
    for (int it = 0; it < NEWT; it++) {
        float g = 0.f, gp = 0.f;
        #pragma unroll
        for (int i = 0; i < 24; i++) {
            float t0 = fmaxf(v[i].x - tau, 0.f); g = fmaf(t0, t0, g); gp += t0;
            float t1 = fmaxf(v[i].y - tau, 0.f); g = fmaf(t1, t1, g); gp += t1;
            float t2 = fmaxf(v[i].z - tau, 0.f); g = fmaf(t2, t2, g); gp += t2;
            float t3 = fmaxf(v[i].w - tau, 0.f); g = fmaf(t3, t3, g); gp += t3;
        }
        #pragma unroll
        for (int o = 16; o; o >>= 1) {
            g  += __shfl_xor_sync(0xffffffffu, g, o);
            gp += __shfl_xor_sync(0xffffffffu, gp, o);
        }
        tau = tau + (g - 1.0f) / fmaxf(2.f * gp, 1e-20f);
        tau = fminf(fmaxf(tau, -1.0f), 0.0f);
    }

    #pragma unroll
    for (int i = 0; i < 24; i++) {
        float t;
        t = fmaxf(v[i].x - tau, 0.f); v[i].x = t * t;
        t = fmaxf(v[i].y - tau, 0.f); v[i].y = t * t;
        t = fmaxf(v[i].z - tau, 0.f); v[i].z = t * t;
        t = fmaxf(v[i].w - tau, 0.f); v[i].w = t * t;
        rp[lane + i * 32] = v[i];
    }
}

// ================= Kernel 4: ctx partial = P @ V (HMMA, K-split x2) =================
#define PV_STR   72
#define PV_STAGE (4 * 64 * PV_STR * 2)
#define PV_SMEM  (2 * PV_STAGE)

__global__ __launch_bounds__(256, 2) void pv_kernel(const float* __restrict__ p)
{
    extern __shared__ char sm[];

    const int tid = threadIdx.x, wid = tid >> 5, lane = tid & 31;
    const int h = blockIdx.y;
    const int row0 = blockIdx.x * 64;
    const int zk = blockIdx.z;              // K half
    const int cbase = zk * 24;

    float acc[4][4];
    #pragma unroll
    for (int j = 0; j < 4; j++)
        #pragma unroll
        for (int q = 0; q < 4; q++) acc[j][q] = 0.f;

    const int arow = lane & 15, ak = (lane >> 4) * 8;
    const int wm = (wid & 3) * 16;
    const int wn = (wid >> 2) * 32;

    const int pr0 = tid >> 4;
    const int pc4 = (tid & 15) * 4;
    const int vdv = tid >> 4;
    const int vj  = (tid & 15) * 4;

    float4 pf_p[4];
    uint2  pf_vh[4], pf_vl[4];

    {
        const int j0 = cbase * 64;
        char* smAh = sm;
        char* smAl = sm + 64 * PV_STR * 2;
        char* smBh = sm + 2 * 64 * PV_STR * 2;
        char* smBl = sm + 3 * 64 * PV_STR * 2;
        #pragma unroll
        for (int t = 0; t < 4; t++) {
            pf_p[t]  = *(const float4*)&p[((size_t)h * kS + row0 + pr0 + t * 16) * kS + j0 + pc4];
            pf_vh[t] = *(const uint2*)&g_vth[((size_t)h * 64 + vdv + t * 16) * kS + j0 + vj];
            pf_vl[t] = *(const uint2*)&g_vtl[((size_t)h * 64 + vdv + t * 16) * kS + j0 + vj];
        }
        #pragma unroll
        for (int t = 0; t < 4; t++) {
            uint32_t h01, h23, l01, l23;
            split4(pf_p[t], h01, h23, l01, l23);
            uint32_t offA = (uint32_t)(pr0 + t * 16) * (PV_STR * 2) + (uint32_t)pc4 * 2;
            *(uint2*)(smAh + offA) = make_uint2(h01, h23);
            *(uint2*)(smAl + offA) = make_uint2(l01, l23);
            uint32_t offB = (uint32_t)(vdv + t * 16) * (PV_STR * 2) + (uint32_t)vj * 2;
            *(uint2*)(smBh + offB) = pf_vh[t];
            *(uint2*)(smBl + offB) = pf_vl[t];
        }
    }
    __syncthreads();

    #pragma unroll 1
    for (int c = 0; c < 24; c++) {
        char* rd = sm + (c & 1) * PV_STAGE;
        char* wr = sm + ((c + 1) & 1) * PV_STAGE;
        const uint32_t ahB = smem_u32(rd);
        const uint32_t alB = ahB + 64 * PV_STR * 2;
        const uint32_t bhB = ahB + 2 * 64 * PV_STR * 2;
        const uint32_t blB = ahB + 3 * 64 * PV_STR * 2;

        if (c < 23) {
            const int j0 = (cbase + c + 1) * 64;
            #pragma unroll
            for (int t = 0; t < 4; t++) {
                pf_p[t]  = *(const float4*)&p[((size_t)h * kS + row0 + pr0 + t * 16) * kS + j0 + pc4];
                pf_vh[t] = *(const uint2*)&g_vth[((size_t)h * 64 + vdv + t * 16) * kS + j0 + vj];
                pf_vl[t] = *(const uint2*)&g_vtl[((size_t)h * 64 + vdv + t * 16) * kS + j0 + vj];
            }
        }

        #pragma unroll
        for (int ks = 0; ks < 4; ks++) {
            uint32_t koff = (uint32_t)(ks * 16 + ak) * 2;
            uint32_t ah[4], al[4];
            ldm_x4(ah, ahB + (uint32_t)(wm + arow) * (PV_STR * 2) + koff);
            ldm_x4(al, alB + (uint32_t)(wm + arow) * (PV_STR * 2) + koff);
            uint32_t bh[2][4], bl[2][4];
            #pragma unroll
            for (int nb = 0; nb < 2; nb++) {
                ldm_x4(bh[nb], bhB + (uint32_t)(wn + nb * 16 + arow) * (PV_STR * 2) + koff);
                ldm_x4(bl[nb], blB + (uint32_t)(wn + nb * 16 + arow) * (PV_STR * 2) + koff);
            }
            #pragma unroll
            for (int nb = 0; nb < 2; nb++) {
                mma16816(acc[nb * 2 + 0], ah, bh[nb][0], bh[nb][2]);
                mma16816(acc[nb * 2 + 1], ah, bh[nb][1], bh[nb][3]);
                mma16816(acc[nb * 2 + 0], ah, bl[nb][0], bl[nb][2]);
                mma16816(acc[nb * 2 + 1], ah, bl[nb][1], bl[nb][3]);
                mma16816(acc[nb * 2 + 0], al, bh[nb][0], bh[nb][2]);
                mma16816(acc[nb * 2 + 1], al, bh[nb][1], bh[nb][3]);
            }
        }

        if (c < 23) {
            char* smAh = wr;
            char* smAl = wr + 64 * PV_STR * 2;
            char* smBh = wr + 2 * 64 * PV_STR * 2;
            char* smBl = wr + 3 * 64 * PV_STR * 2;
            #pragma unroll
            for (int t = 0; t < 4; t++) {
                uint32_t h01, h23, l01, l23;
                split4(pf_p[t], h01, h23, l01, l23);
                uint32_t offA = (uint32_t)(pr0 + t * 16) * (PV_STR * 2) + (uint32_t)pc4 * 2;
                *(uint2*)(smAh + offA) = make_uint2(h01, h23);
                *(uint2*)(smAl + offA) = make_uint2(l01, l23);
                uint32_t offB = (uint32_t)(vdv + t * 16) * (PV_STR * 2) + (uint32_t)vj * 2;
                *(uint2*)(smBh + offB) = pf_vh[t];
                *(uint2*)(smBl + offB) = pf_vl[t];
            }
        }
        __syncthreads();
    }

    // epilogue: fp32 partials
    const int gId = lane >> 2, tig = lane & 3;
    #pragma unroll
    for (int f = 0; f < 4; f++) {
        int cc = wn + (f >> 1) * 16 + (f & 1) * 8 + tig * 2;
        int r_lo = row0 + wm + gId;
        *(float2*)&g_pvp[zk][(size_t)r_lo * kD + h * 64 + cc] =
            make_float2(acc[f][0], acc[f][1]);
        *(float2*)&g_pvp[zk][(size_t)(r_lo + 8) * kD + h * 64 + cc] =
            make_float2(acc[f][2], acc[f][3]);
    }
}

// ================= Kernel 4b: combine K-split partials -> ctx hi/lo bf16 =================
__global__ __launch_bounds__(256) void combine_kernel()
{
    int i = blockIdx.x * 256 + threadIdx.x;    // float4 index
    float4 a = ((const float4*)g_pvp[0])[i];
    float4 b = ((const float4*)g_pvp[1])[i];
    a.x += b.x; a.y += b.y; a.z += b.z; a.w += b.w;
    uint32_t h01, h23, l01, l23;
    split4(a, h01, h23, l01, l23);
    ((uint2*)g_cth)[i] = make_uint2(h01, h23);
    ((uint2*)g_ctl)[i] = make_uint2(l01, l23);
}

// ================= Kernel 5: out = ctx @ Wo + bo (HMMA) =================
__global__ __launch_bounds__(256) void outmm_kernel(const float* __restrict__ bo)
{
    __shared__ __align__(16) char s[4 * 64 * QK_STR * 2];
    char* sAh = s;
    char* sAl = s + 64 * QK_STR * 2;
    char* sBh = s + 2 * 64 * QK_STR * 2;
    char* sBl = s + 3 * 64 * QK_STR * 2;

    const int m0 = blockIdx.x * 64;
    const int n0 = blockIdx.y * 64;

    const int tid = threadIdx.x, wid = tid >> 5, lane = tid & 31;
    const uint32_t ahB = smem_u32(sAh), alB = smem_u32(sAl);
    const uint32_t bhB = smem_u32(sBh), blB = smem_u32(sBl);

    const int wm = (wid & 3) * 16;
    const int wn = (wid >> 2) * 32;
    const int arow = lane & 15, ak = (lane >> 4) * 8;

    float acc[4][4];
    #pragma unroll
    for (int j = 0; j < 4; j++)
        #pragma unroll
        for (int q = 0; q < 4; q++) acc[j][q] = 0.f;

    #pragma unroll 1
    for (int k0 = 0; k0 < kD; k0 += 64) {
        __syncthreads();
        #pragma unroll
        for (int t = 0; t < 4; t++) {
            int i = tid + t * 256;
            int r = i >> 4, c4 = (i & 15) * 4;
            uint32_t off = (uint32_t)r * (QK_STR * 2) + (uint32_t)c4 * 2;
            size_t ax = (size_t)(m0 + r) * kD + k0 + c4;
            *(uint2*)(sAh + off) = *(const uint2*)&g_cth[ax];
            *(uint2*)(sAl + off) = *(const uint2*)&g_ctl[ax];
            size_t bx = ((size_t)3 * kD + n0 + r) * kD + k0 + c4;
            *(uint2*)(sBh + off) = *(const uint2*)&g_wth[bx];
            *(uint2*)(sBl + off) = *(const uint2*)&g_wtl[bx];
        }
        __syncthreads();

        #pragma unroll
        for (int ks = 0; ks < 4; ks++) {
            uint32_t koff = (uint32_t)(ks * 16 + ak) * 2;
            uint32_t ah[4], al[4];
            ldm_x4(ah, ahB + (uint32_t)(wm + arow) * (QK_STR * 2) + koff);
            ldm_x4(al, alB + (uint32_t)(wm + arow) * (QK_STR * 2) + koff);
            uint32_t bh[2][4], bl[2][4];
            #pragma unroll
            for (int nb = 0; nb < 2; nb++) {
                ldm_x4(bh[nb], bhB + (uint32_t)(wn + nb * 16 + arow) * (QK_STR * 2) + koff);
                ldm_x4(bl[nb], blB + (uint32_t)(wn + nb * 16 + arow) * (QK_STR * 2) + koff);
            }
            #pragma unroll
            for (int nb = 0; nb < 2; nb++) {
                mma16816(acc[nb * 2 + 0], ah, bh[nb][0], bh[nb][2]);
                mma16816(acc[nb * 2 + 1], ah, bh[nb][1], bh[nb][3]);
                mma16816(acc[nb * 2 + 0], ah, bl[nb][0], bl[nb][2]);
                mma16816(acc[nb * 2 + 1], ah, bl[nb][1], bl[nb][3]);
                mma16816(acc[nb * 2 + 0], al, bh[nb][0], bh[nb][2]);
                mma16816(acc[nb * 2 + 1], al, bh[nb][1], bh[nb][3]);
            }
        }
    }

    const int gId = lane >> 2, tig = lane & 3;
    #pragma unroll
    for (int nf = 0; nf < 4; nf++) {
        int dkc = wn + nf * 8 + tig * 2;
        int m_lo = m0 + wm + gId;
        float b0v = bo[n0 + dkc], b1v = bo[n0 + dkc + 1];
        *(float2*)&g_ctx[(size_t)m_lo * kD + n0 + dkc] =
            make_float2(acc[nf][0] + b0v, acc[nf][1] + b1v);
        *(float2*)&g_ctx[(size_t)(m_lo + 8) * kD + n0 + dkc] =
            make_float2(acc[nf][2] + b0v, acc[nf][3] + b1v);
    }
}

// ================= Kernel 6: residual + LayerNorm =================
__global__ __launch_bounds__(256) void ln_kernel(
    const float* __restrict__ x,
    const float* __restrict__ gamma, const float* __restrict__ beta,
    float* __restrict__ out)
{
    __shared__ float sC[16 * kD];

    const int m0  = blockIdx.x * 16;
    const int tid = threadIdx.x;

    for (int i = tid; i < 2048; i += 256) {
        float4 c = ((const float4*)&g_ctx[(size_t)m0 * kD])[i];
        float4 r = ((const float4*)&x[(size_t)m0 * kD])[i];
        c.x += r.x; c.y += r.y; c.z += r.z; c.w += r.w;
        ((float4*)sC)[i] = c;
    }
    __syncthreads();

    const int wid = tid >> 5, lane = tid & 31;
    #pragma unroll 1
    for (int rr = 0; rr < 2; rr++) {
        int r = wid * 2 + rr;
        float s = 0.f, ss = 0.f;
        for (int i = lane; i < kD; i += 32) {
            float v = sC[r * kD + i];
            s += v; ss = fmaf(v, v, ss);
        }
        #pragma unroll
        for (int o = 16; o; o >>= 1) {
            s  += __shfl_xor_sync(0xffffffffu, s, o);
            ss += __shfl_xor_sync(0xffffffffu, ss, o);
        }
        float mu  = s * (1.f / kD);
        float var = ss * (1.f / kD) - mu * mu;
        float inv = rsqrtf(var + 1e-6f);
        for (int i = lane; i < kD; i += 32) {
            float v = sC[r * kD + i];
            out[(size_t)(m0 + r) * kD + i] = (v - mu) * inv * gamma[i] + beta[i];
        }
    }
}

// ================= launcher =================
extern "C" void kernel_launch(void* const* d_in, const int* in_sizes, int n_in,
                              void* d_out, int out_size)
{
    const float* x     = (const float*)d_in[0];
    const float* Wq    = (const float*)d_in[1];
    const float* bq    = (const float*)d_in[2];
    const float* Wk    = (const float*)d_in[3];
    const float* bk    = (const float*)d_in[4];
    const float* Wv    = (const float*)d_in[5];
    const float* bv    = (const float*)d_in[6];
    const float* Wo    = (const float*)d_in[7];
    const float* bo    = (const float*)d_in[8];
    const float* gamma = (const float*)d_in[9];
    const float* beta  = (const float*)d_in[10];

    float* out  = (float*)d_out;
    float* attn = out + (size_t)kS * kD;

    cudaFuncSetAttribute(logits_kernel, cudaFuncAttributeMaxDynamicSharedMemorySize, LG_SMEM);
    cudaFuncSetAttribute(pv_kernel,     cudaFuncAttributeMaxDynamicSharedMemorySize, PV_SMEM);

    xsplit_kernel<<<kS * kD / 4 / 256, 256>>>(x);
    wsplit_kernel<<<dim3(kD * kD / 4 / 256, 4), 256>>>(Wq, Wk, Wv, Wo);
    qkv_kernel<<<dim3(48, 8, 3), 256>>>(bq, bk, bv);
    vsplit_kernel<<<dim3(192, 8), 256>>>();
    logits_kernel<<<dim3(24, 24, 8), 256, LG_SMEM>>>(attn);
    entmax_kernel<<<dim3(kS / 8, kH), 256>>>(attn);
    pv_kernel<<<dim3(48, 8, 2), 256, PV_SMEM>>>(attn);
    combine_kernel<<<kS * kD / 4 / 256, 256>>>();
    outmm_kernel<<<dim3(48, 8), 256>>>(bo);
    ln_kernel<<<kS / 16, 256>>>(x, gamma, beta, out);
}